// round 8
// baseline (speedup 1.0000x reference)
#include <cuda_runtime.h>
#include <cuda_bf16.h>
#include <cstdint>

#define N_HEAD 16
#define C_EMBD 1024
#define HD     64
#define BATCH  4
#define SEQ    2048
#define MTOT   (BATCH * SEQ)   // 8192

// ---------------- scratch (device globals: allocation-free) ----------------
__device__ __nv_bfloat16 g_Qhi[BATCH * N_HEAD * SEQ * HD];
__device__ __nv_bfloat16 g_Qlo[BATCH * N_HEAD * SEQ * HD];
__device__ __nv_bfloat16 g_Khi[BATCH * N_HEAD * SEQ * HD];
__device__ __nv_bfloat16 g_Klo[BATCH * N_HEAD * SEQ * HD];
__device__ __nv_bfloat16 g_Vhi[BATCH * N_HEAD * SEQ * HD];
__device__ __nv_bfloat16 g_Vlo[BATCH * N_HEAD * SEQ * HD];

__device__ __nv_bfloat16 g_Xhi[MTOT * C_EMBD];
__device__ __nv_bfloat16 g_Xlo[MTOT * C_EMBD];
__device__ __nv_bfloat16 g_Yhi[MTOT * C_EMBD];
__device__ __nv_bfloat16 g_Ylo[MTOT * C_EMBD];
__device__ __nv_bfloat16 g_Wahi[3 * C_EMBD * C_EMBD];  // [N=3072][K=1024]
__device__ __nv_bfloat16 g_Walo[3 * C_EMBD * C_EMBD];
__device__ __nv_bfloat16 g_Wphi[C_EMBD * C_EMBD];      // [N=1024][K=1024]
__device__ __nv_bfloat16 g_Wplo[C_EMBD * C_EMBD];

// ---------------- helpers ----------------
__device__ __forceinline__ uint32_t smem_u32(const void* p) {
    uint32_t a;
    asm("{ .reg .u64 t; cvta.to.shared.u64 t, %1; cvt.u32.u64 %0, t; }" : "=r"(a) : "l"(p));
    return a;
}

__device__ __forceinline__ void ldsm_x4(uint32_t& r0, uint32_t& r1,
                                        uint32_t& r2, uint32_t& r3, uint32_t addr) {
    asm volatile("ldmatrix.sync.aligned.m8n8.x4.shared.b16 {%0,%1,%2,%3}, [%4];"
                 : "=r"(r0), "=r"(r1), "=r"(r2), "=r"(r3) : "r"(addr));
}

__device__ __forceinline__ void ldsm_x4_t(uint32_t& r0, uint32_t& r1,
                                          uint32_t& r2, uint32_t& r3, uint32_t addr) {
    asm volatile("ldmatrix.sync.aligned.m8n8.x4.trans.shared.b16 {%0,%1,%2,%3}, [%4];"
                 : "=r"(r0), "=r"(r1), "=r"(r2), "=r"(r3) : "r"(addr));
}

__device__ __forceinline__ void mma_bf16(float* c, const uint32_t* a, const uint32_t* b) {
    asm volatile(
        "mma.sync.aligned.m16n8k16.row.col.f32.bf16.bf16.f32 "
        "{%0,%1,%2,%3}, {%4,%5,%6,%7}, {%8,%9}, {%0,%1,%2,%3};"
        : "+f"(c[0]), "+f"(c[1]), "+f"(c[2]), "+f"(c[3])
        : "r"(a[0]), "r"(a[1]), "r"(a[2]), "r"(a[3]), "r"(b[0]), "r"(b[1]));
}

__device__ __forceinline__ void cp_async16(uint32_t dst, const void* src) {
    asm volatile("cp.async.cg.shared.global [%0], [%1], 16;" :: "r"(dst), "l"(src));
}
__device__ __forceinline__ void cp_commit() {
    asm volatile("cp.async.commit_group;");
}
template <int N>
__device__ __forceinline__ void cp_wait() {
    asm volatile("cp.async.wait_group %0;" :: "n"(N));
}

// split two floats into bf16 hi pair + bf16 lo (residual) pair, packed b16x2
__device__ __forceinline__ void split2(float x, float y, uint32_t& hi, uint32_t& lo) {
    __nv_bfloat162 h = __floats2bfloat162_rn(x, y);
    __nv_bfloat162 l = __floats2bfloat162_rn(x - __bfloat162float(h.x),
                                             y - __bfloat162float(h.y));
    hi = *(uint32_t*)&h;
    lo = *(uint32_t*)&l;
}

// ---------------- prep kernels ----------------
__global__ __launch_bounds__(256)
void split_x_kernel(const float* __restrict__ X) {
    int i = blockIdx.x * 256 + threadIdx.x;           // float4 index
    float4 v = ((const float4*)X)[i];
    __nv_bfloat16 h0 = __float2bfloat16(v.x), h1 = __float2bfloat16(v.y);
    __nv_bfloat16 h2 = __float2bfloat16(v.z), h3 = __float2bfloat16(v.w);
    ((__nv_bfloat162*)g_Xhi)[2*i+0] = __nv_bfloat162(h0, h1);
    ((__nv_bfloat162*)g_Xhi)[2*i+1] = __nv_bfloat162(h2, h3);
    __nv_bfloat16 l0 = __float2bfloat16(v.x - __bfloat162float(h0));
    __nv_bfloat16 l1 = __float2bfloat16(v.y - __bfloat162float(h1));
    __nv_bfloat16 l2 = __float2bfloat16(v.z - __bfloat162float(h2));
    __nv_bfloat16 l3 = __float2bfloat16(v.w - __bfloat162float(h3));
    ((__nv_bfloat162*)g_Xlo)[2*i+0] = __nv_bfloat162(l0, l1);
    ((__nv_bfloat162*)g_Xlo)[2*i+1] = __nv_bfloat162(l2, l3);
}

// transpose + split:  W[K, N] fp32  ->  Wt_hi/lo[N, K] bf16
__global__ __launch_bounds__(256)
void wsplit_kernel(const float* __restrict__ W, int which, int N) {
    __shared__ float t[32][33];
    __nv_bfloat16* Hi = which ? g_Wphi : g_Wahi;
    __nv_bfloat16* Lo = which ? g_Wplo : g_Walo;
    const int K = C_EMBD;
    int n0 = blockIdx.x * 32, k0 = blockIdx.y * 32;
    int tx = threadIdx.x, ty = threadIdx.y;
#pragma unroll
    for (int s = 0; s < 4; s++) {
        int i = ty + 8 * s;
        t[i][tx] = W[(size_t)(k0 + i) * N + n0 + tx];
    }
    __syncthreads();
#pragma unroll
    for (int s = 0; s < 4; s++) {
        int i = ty + 8 * s;
        float v = t[tx][i];                            // W[k0+tx][n0+i]
        __nv_bfloat16 h = __float2bfloat16(v);
        Hi[(size_t)(n0 + i) * K + k0 + tx] = h;
        Lo[(size_t)(n0 + i) * K + k0 + tx] = __float2bfloat16(v - __bfloat162float(h));
    }
}

// ---------------- HMMA GEMM (bf16x3, fp32 accumulate) ----------------
// 512 threads, CTA tile 128x128, warp tile 32x32, cp.async 3-stage, BK=32.
// Pass-interleaved MMA order: 8 independent accumulators between same-acc reuse.
#define BKC     32
#define NCHUNK  (C_EMBD / BKC)          // 32
#define ROWB    80                       // smem row pitch bytes
#define MATB    (128 * ROWB)             // 10240 B
#define STAGEB  (4 * MATB)               // 40960 B (Ah, Al, Bh, Bl)
#define NSTAGE  3
#define AH_OFF  0
#define AL_OFF  MATB
#define BH_OFF  (2 * MATB)
#define BL_OFF  (3 * MATB)

template <int MODE>   // 0: QKV gemm (split-scatter to Q/K/V hi/lo), 1: proj gemm
__global__ __launch_bounds__(512, 1)
void mma_gemm(const float* __restrict__ bias, float* __restrict__ Cout, int N)
{
    extern __shared__ char smem[];

    const __nv_bfloat16* Ahi = (MODE == 0) ? g_Xhi : g_Yhi;
    const __nv_bfloat16* Alo = (MODE == 0) ? g_Xlo : g_Ylo;
    const __nv_bfloat16* Bhi = (MODE == 0) ? g_Wahi : g_Wphi;
    const __nv_bfloat16* Blo = (MODE == 0) ? g_Walo : g_Wplo;

    const int K = C_EMBD;
    int tid = threadIdx.x;
    int lane = tid & 31, wid = tid >> 5;
    int wm = wid & 3, wn = wid >> 2;                  // warp tile 32(M) x 32(N)
    int bn = blockIdx.x * 128;
    int bm = blockIdx.y * 128;

    uint32_t sb = smem_u32(smem);

    int r_ld = tid >> 2;                  // 0..127
    int q_ld = tid & 3;                   // 16B slot
    const __nv_bfloat16* pAh = Ahi + (size_t)(bm + r_ld) * K + q_ld * 8;
    const __nv_bfloat16* pAl = Alo + (size_t)(bm + r_ld) * K + q_ld * 8;
    const __nv_bfloat16* pBh = Bhi + (size_t)(bn + r_ld) * K + q_ld * 8;
    const __nv_bfloat16* pBl = Blo + (size_t)(bn + r_ld) * K + q_ld * 8;
    uint32_t stoff = (uint32_t)(r_ld * ROWB + q_ld * 16);

    uint32_t a_row = (uint32_t)(wm * 32 + (lane & 15));          // + mf*16
    uint32_t a_colb = (uint32_t)(((lane >> 4) << 3) * 2);        // + ks*32
    int bq = lane >> 3;
    uint32_t b_row = (uint32_t)(wn * 32 + ((bq >> 1) << 3) + (lane & 7));  // + nb*16
    uint32_t b_colb = (uint32_t)(((bq & 1) << 3) * 2);                     // + ks*32

    float acc[2][4][4];
#pragma unroll
    for (int i = 0; i < 2; i++)
#pragma unroll
        for (int j = 0; j < 4; j++)
#pragma unroll
            for (int k = 0; k < 4; k++) acc[i][j][k] = 0.0f;

    // prologue: stages 0,1
#pragma unroll
    for (int st = 0; st < 2; st++) {
        uint32_t d = sb + st * STAGEB + stoff;
        int k0 = st * BKC;
        cp_async16(d + AH_OFF, pAh + k0);
        cp_async16(d + AL_OFF, pAl + k0);
        cp_async16(d + BH_OFF, pBh + k0);
        cp_async16(d + BL_OFF, pBl + k0);
        cp_commit();
    }

    int stage_c = 0;
    int stage_l = 2;
    for (int ch = 0; ch < NCHUNK; ch++) {
        cp_wait<1>();
        __syncthreads();

        if (ch + 2 < NCHUNK) {
            uint32_t d = sb + stage_l * STAGEB + stoff;
            int k0 = (ch + 2) * BKC;
            cp_async16(d + AH_OFF, pAh + k0);
            cp_async16(d + AL_OFF, pAl + k0);
            cp_async16(d + BH_OFF, pBh + k0);
            cp_async16(d + BL_OFF, pBl + k0);
        }
        cp_commit();

        uint32_t stage = sb + stage_c * STAGEB;
#pragma unroll
        for (int ks = 0; ks < 2; ks++) {
            uint32_t kb = (uint32_t)(ks * 32);
            uint32_t ah[2][4], al[2][4];
#pragma unroll
            for (int mf = 0; mf < 2; mf++) {
                uint32_t ra = stage + (a_row + mf * 16) * ROWB + a_colb + kb;
                ldsm_x4(ah[mf][0], ah[mf][1], ah[mf][2], ah[mf][3], ra + AH_OFF);
                ldsm_x4(al[mf][0], al[mf][1], al[mf][2], al[mf][3], ra + AL_OFF);
            }
            uint32_t bh[4][2], bl[4][2];
#pragma unroll
            for (int nb = 0; nb < 2; nb++) {
                uint32_t rb = stage + (b_row + nb * 16) * ROWB + b_colb + kb;
                ldsm_x4(bh[2*nb][0], bh[2*nb][1], bh[2*nb+1][0], bh[2*nb+1][1], rb + BH_OFF);
                ldsm_x4(bl[2*nb][0], bl[2*nb][1], bl[2*nb+1][0], bl[2*nb+1][1], rb + BL_OFF);
            }
            // pass-interleaved: all 8 accumulators between same-acc reuses
#pragma unroll
            for (int mf = 0; mf < 2; mf++)
#pragma unroll
                for (int nf = 0; nf < 4; nf++)
                    mma_bf16(acc[mf][nf], ah[mf], bh[nf]);
#pragma unroll
            for (int mf = 0; mf < 2; mf++)
#pragma unroll
                for (int nf = 0; nf < 4; nf++)
                    mma_bf16(acc[mf][nf], ah[mf], bl[nf]);
#pragma unroll
            for (int mf = 0; mf < 2; mf++)
#pragma unroll
                for (int nf = 0; nf < 4; nf++)
                    mma_bf16(acc[mf][nf], al[mf], bh[nf]);
        }

        stage_c = (stage_c == NSTAGE - 1) ? 0 : stage_c + 1;
        stage_l = (stage_l == NSTAGE - 1) ? 0 : stage_l + 1;
    }

    // epilogue: bias + write
#pragma unroll
    for (int mf = 0; mf < 2; mf++) {
#pragma unroll
        for (int nf = 0; nf < 4; nf++) {
            int m0 = bm + wm * 32 + mf * 16 + (lane >> 2);
            int n0 = bn + wn * 32 + nf * 8 + 2 * (lane & 3);
#pragma unroll
            for (int half = 0; half < 2; half++) {
                int m = m0 + half * 8;
                float v0 = acc[mf][nf][2 * half + 0] + bias[n0];
                float v1 = acc[mf][nf][2 * half + 1] + bias[n0 + 1];
                if (MODE == 0) {
                    int bb = m >> 11, t = m & 2047;
                    int which = n0 >> 10;
                    int cc = n0 & 1023;
                    int h = cc >> 6, d = cc & 63;
                    __nv_bfloat16* Hi = (which == 0) ? g_Qhi : (which == 1) ? g_Khi : g_Vhi;
                    __nv_bfloat16* Lo = (which == 0) ? g_Qlo : (which == 1) ? g_Klo : g_Vlo;
                    size_t idx = ((((size_t)bb * N_HEAD) + h) * SEQ + t) * HD + d;
                    __nv_bfloat16 h0 = __float2bfloat16(v0);
                    __nv_bfloat16 h1 = __float2bfloat16(v1);
                    *(__nv_bfloat162*)&Hi[idx] = __nv_bfloat162(h0, h1);
                    *(__nv_bfloat162*)&Lo[idx] = __nv_bfloat162(
                        __float2bfloat16(v0 - __bfloat162float(h0)),
                        __float2bfloat16(v1 - __bfloat162float(h1)));
                } else {
                    *(float2*)&Cout[(size_t)m * N + n0] = make_float2(v0, v1);
                }
            }
        }
    }
}

// ---------------------------------------------------------------------------
// HMMA flash attention: CTA = (b*h, 64-query block), 4 warps x 16 rows.
// Pass-interleaved MMA ordering throughout.
// ---------------------------------------------------------------------------
#define FPITCH 144    // smem row pitch (bytes)
#define FTILE  (64 * FPITCH)   // 9216 B

__global__ __launch_bounds__(128)
void flash_mma_kernel()
{
    extern __shared__ char fsm[];
    char* pQH = fsm;
    char* pKH = fsm + 2 * FTILE;
    char* pVH = fsm + 4 * FTILE;
    const uint32_t QH = smem_u32(pQH);
    const uint32_t KH = smem_u32(pKH);
    const uint32_t VH = smem_u32(pVH);

    int tid = threadIdx.x, lane = tid & 31, w = tid >> 5;
    int qb = (int)(gridDim.x - 1) - (int)blockIdx.x;    // heavy blocks first
    int bh = blockIdx.y;
    int q0 = qb * 64;
    size_t base = (size_t)bh * SEQ * HD;

    // load Q hi/lo tile
    {
        int r = tid >> 3, s = tid & 7;
#pragma unroll
        for (int it = 0; it < 4; it++) {
            int rr = r + it * 16;
            size_t off = base + (size_t)(q0 + rr) * HD + s * 8;
            *(uint4*)(pQH + rr * FPITCH + s * 16) = *(const uint4*)(g_Qhi + off);
            *(uint4*)(pQH + FTILE + rr * FPITCH + s * 16) = *(const uint4*)(g_Qlo + off);
        }
    }

    float m0 = -1e30f, m1 = -1e30f, l0 = 0.0f, l1 = 0.0f;
    float O[8][4];
#pragma unroll
    for (int i = 0; i < 8; i++)
#pragma unroll
        for (int j = 0; j < 4; j++) O[i][j] = 0.0f;

    for (int kb = 0; kb <= qb; kb++) {
        __syncthreads();
        int k0 = kb * 64;
        {
            int r = tid >> 3, s = tid & 7;
#pragma unroll
            for (int it = 0; it < 4; it++) {
                int rr = r + it * 16;
                size_t off = base + (size_t)(k0 + rr) * HD + s * 8;
                *(uint4*)(pKH + rr * FPITCH + s * 16) = *(const uint4*)(g_Khi + off);
                *(uint4*)(pKH + FTILE + rr * FPITCH + s * 16) = *(const uint4*)(g_Klo + off);
                *(uint4*)(pVH + rr * FPITCH + s * 16) = *(const uint4*)(g_Vhi + off);
                *(uint4*)(pVH + FTILE + rr * FPITCH + s * 16) = *(const uint4*)(g_Vlo + off);
            }
        }
        __syncthreads();

        // ---- S = Q K^T (bf16x3, pass-interleaved) ----
        float S[8][4];
#pragma unroll
        for (int i = 0; i < 8; i++)
#pragma unroll
            for (int j = 0; j < 4; j++) S[i][j] = 0.0f;

        int bq = lane >> 3;
#pragma unroll
        for (int s = 0; s < 4; s++) {
            uint32_t ah[4], al[4];
            uint32_t ra = QH + (w * 16 + (lane & 15)) * FPITCH + (lane >> 4) * 16 + s * 32;
            ldsm_x4(ah[0], ah[1], ah[2], ah[3], ra);
            ldsm_x4(al[0], al[1], al[2], al[3], ra + FTILE);
            uint32_t bh_[4][4], bl_[4][4];
#pragma unroll
            for (int nt = 0; nt < 4; nt++) {
                uint32_t rb = KH + (nt * 16 + ((bq >> 1) << 3) + (lane & 7)) * FPITCH
                            + (bq & 1) * 16 + s * 32;
                ldsm_x4(bh_[nt][0], bh_[nt][1], bh_[nt][2], bh_[nt][3], rb);
                ldsm_x4(bl_[nt][0], bl_[nt][1], bl_[nt][2], bl_[nt][3], rb + FTILE);
            }
#pragma unroll
            for (int nt = 0; nt < 4; nt++) {
                mma_bf16(S[2*nt],   ah, &bh_[nt][0]);
                mma_bf16(S[2*nt+1], ah, &bh_[nt][2]);
            }
#pragma unroll
            for (int nt = 0; nt < 4; nt++) {
                mma_bf16(S[2*nt],   ah, &bl_[nt][0]);
                mma_bf16(S[2*nt+1], ah, &bl_[nt][2]);
            }
#pragma unroll
            for (int nt = 0; nt < 4; nt++) {
                mma_bf16(S[2*nt],   al, &bh_[nt][0]);
                mma_bf16(S[2*nt+1], al, &bh_[nt][2]);
            }
        }

        // ---- scale + causal mask ----
#pragma unroll
        for (int nb = 0; nb < 8; nb++)
#pragma unroll
            for (int e = 0; e < 4; e++) S[nb][e] *= 0.125f;

        if (kb == qb) {
            int rl0 = w * 16 + (lane >> 2);
#pragma unroll
            for (int nb = 0; nb < 8; nb++) {
                int c = nb * 8 + 2 * (lane & 3);
                if (c     > rl0)     S[nb][0] = -1e30f;
                if (c + 1 > rl0)     S[nb][1] = -1e30f;
                if (c     > rl0 + 8) S[nb][2] = -1e30f;
                if (c + 1 > rl0 + 8) S[nb][3] = -1e30f;
            }
        }

        // ---- online softmax ----
        float mx0 = -1e30f, mx1 = -1e30f;
#pragma unroll
        for (int nb = 0; nb < 8; nb++) {
            mx0 = fmaxf(mx0, fmaxf(S[nb][0], S[nb][1]));
            mx1 = fmaxf(mx1, fmaxf(S[nb][2], S[nb][3]));
        }
        mx0 = fmaxf(mx0, __shfl_xor_sync(0xffffffffu, mx0, 1));
        mx0 = fmaxf(mx0, __shfl_xor_sync(0xffffffffu, mx0, 2));
        mx1 = fmaxf(mx1, __shfl_xor_sync(0xffffffffu, mx1, 1));
        mx1 = fmaxf(mx1, __shfl_xor_sync(0xffffffffu, mx1, 2));
        float mn0 = fmaxf(m0, mx0), mn1 = fmaxf(m1, mx1);
        float corr0 = __expf(m0 - mn0), corr1 = __expf(m1 - mn1);
        float s0 = 0.0f, s1 = 0.0f;
#pragma unroll
        for (int nb = 0; nb < 8; nb++) {
            S[nb][0] = __expf(S[nb][0] - mn0); s0 += S[nb][0];
            S[nb][1] = __expf(S[nb][1] - mn0); s0 += S[nb][1];
            S[nb][2] = __expf(S[nb][2] - mn1); s1 += S[nb][2];
            S[nb][3] = __expf(S[nb][3] - mn1); s1 += S[nb][3];
        }
        s0 += __shfl_xor_sync(0xffffffffu, s0, 1);
        s0 += __shfl_xor_sync(0xffffffffu, s0, 2);
        s1 += __shfl_xor_sync(0xffffffffu, s1, 1);
        s1 += __shfl_xor_sync(0xffffffffu, s1, 2);
        l0 = l0 * corr0 + s0;
        l1 = l1 * corr1 + s1;
        m0 = mn0; m1 = mn1;
#pragma unroll
        for (int nb = 0; nb < 8; nb++) {
            O[nb][0] *= corr0; O[nb][1] *= corr0;
            O[nb][2] *= corr1; O[nb][3] *= corr1;
        }

        // ---- O += P V (bf16x3, pass-interleaved) ----
#pragma unroll
        for (int s = 0; s < 4; s++) {
            uint32_t pa_h[4], pa_l[4];
            split2(S[2*s][0],   S[2*s][1],   pa_h[0], pa_l[0]);
            split2(S[2*s][2],   S[2*s][3],   pa_h[1], pa_l[1]);
            split2(S[2*s+1][0], S[2*s+1][1], pa_h[2], pa_l[2]);
            split2(S[2*s+1][2], S[2*s+1][3], pa_h[3], pa_l[3]);
            uint32_t vh[4][4], vl[4][4];
#pragma unroll
            for (int nt = 0; nt < 4; nt++) {
                uint32_t rv = VH + (s * 16 + (lane & 7) + ((lane >> 3) & 1) * 8) * FPITCH
                            + nt * 32 + (lane >> 4) * 16;
                ldsm_x4_t(vh[nt][0], vh[nt][1], vh[nt][2], vh[nt][3], rv);
                ldsm_x4_t(vl[nt][0], vl[nt][1], vl[nt][2], vl[nt][3], rv + FTILE);
            }
#pragma unroll
            for (int nt = 0; nt < 4; nt++) {
                mma_bf16(O[2*nt],   pa_h, &vh[nt][0]);
                mma_bf16(O[2*nt+1], pa_h, &vh[nt][2]);
            }
#pragma unroll
            for (int nt = 0; nt < 4; nt++) {
                mma_bf16(O[2*nt],   pa_h, &vl[nt][0]);
                mma_bf16(O[2*nt+1], pa_h, &vl[nt][2]);
            }
#pragma unroll
            for (int nt = 0; nt < 4; nt++) {
                mma_bf16(O[2*nt],   pa_l, &vh[nt][0]);
                mma_bf16(O[2*nt+1], pa_l, &vh[nt][2]);
            }
        }
    }

    // ---- normalize + write Y (bf16 hi/lo, [B,T,C]) ----
    int b = bh >> 4, h = bh & 15;
    int r0g = q0 + w * 16 + (lane >> 2);
    int dcol = 2 * (lane & 3);
    float inv0 = 1.0f / l0, inv1 = 1.0f / l1;
#pragma unroll
    for (int nb = 0; nb < 8; nb++) {
        int d = nb * 8 + dcol;
        {
            float f0 = O[nb][0] * inv0, f1 = O[nb][1] * inv0;
            size_t idx = ((size_t)(b * SEQ + r0g)) * C_EMBD + h * HD + d;
            __nv_bfloat16 h0 = __float2bfloat16(f0), h1 = __float2bfloat16(f1);
            *(__nv_bfloat162*)&g_Yhi[idx] = __nv_bfloat162(h0, h1);
            *(__nv_bfloat162*)&g_Ylo[idx] = __nv_bfloat162(
                __float2bfloat16(f0 - __bfloat162float(h0)),
                __float2bfloat16(f1 - __bfloat162float(h1)));
        }
        {
            float f2 = O[nb][2] * inv1, f3 = O[nb][3] * inv1;
            size_t idx = ((size_t)(b * SEQ + r0g + 8)) * C_EMBD + h * HD + d;
            __nv_bfloat16 h2 = __float2bfloat16(f2), h3 = __float2bfloat16(f3);
            *(__nv_bfloat162*)&g_Yhi[idx] = __nv_bfloat162(h2, h3);
            *(__nv_bfloat162*)&g_Ylo[idx] = __nv_bfloat162(
                __float2bfloat16(f2 - __bfloat162float(h2)),
                __float2bfloat16(f3 - __bfloat162float(h3)));
        }
    }
}

// ---------------------------------------------------------------------------
extern "C" void kernel_launch(void* const* d_in, const int* in_sizes, int n_in,
                              void* d_out, int out_size)
{
    const float* x      = (const float*)d_in[0];
    const float* W_attn = (const float*)d_in[1];
    const float* b_attn = (const float*)d_in[2];
    const float* W_proj = (const float*)d_in[3];
    const float* b_proj = (const float*)d_in[4];
    float* out = (float*)d_out;

    (void)in_sizes; (void)n_in; (void)out_size;

    static const int FLASH_SMEM = 6 * FTILE;                        // 55296 B
    static const int GEMM_SMEM  = NSTAGE * STAGEB;                  // 122880 B
    cudaFuncSetAttribute(flash_mma_kernel,
                         cudaFuncAttributeMaxDynamicSharedMemorySize, FLASH_SMEM);
    cudaFuncSetAttribute(mma_gemm<0>,
                         cudaFuncAttributeMaxDynamicSharedMemorySize, GEMM_SMEM);
    cudaFuncSetAttribute(mma_gemm<1>,
                         cudaFuncAttributeMaxDynamicSharedMemorySize, GEMM_SMEM);

    // 0) prep: split x; transpose+split weights
    split_x_kernel<<<MTOT * C_EMBD / 4 / 256, 256>>>(x);
    wsplit_kernel<<<dim3(3 * C_EMBD / 32, C_EMBD / 32), dim3(32, 8)>>>(W_attn, 0, 3 * C_EMBD);
    wsplit_kernel<<<dim3(C_EMBD / 32, C_EMBD / 32), dim3(32, 8)>>>(W_proj, 1, C_EMBD);

    // 1) QKV GEMM (HMMA bf16x3) + bias -> Q/K/V bf16 hi/lo [B,H,T,hd]
    mma_gemm<0><<<dim3(3 * C_EMBD / 128, MTOT / 128), 512, GEMM_SMEM>>>(
        b_attn, nullptr, 3 * C_EMBD);

    // 2) causal flash attention (HMMA bf16x3) -> Yhi/Ylo
    flash_mma_kernel<<<dim3(SEQ / 64, BATCH * N_HEAD), 128, FLASH_SMEM>>>();

    // 3) output projection (HMMA bf16x3) + bias -> d_out
    mma_gemm<1><<<dim3(C_EMBD / 128, MTOT / 128), 512, GEMM_SMEM>>>(
        b_proj, out, C_EMBD);
}

// round 9
// speedup vs baseline: 1.2498x; 1.2498x over previous
#include <cuda_runtime.h>
#include <cuda_bf16.h>
#include <cuda_fp16.h>
#include <cstdint>

#define N_HEAD 16
#define C_EMBD 1024
#define HD     64
#define BATCH  4
#define SEQ    2048
#define MTOT   (BATCH * SEQ)   // 8192

// ---------------- scratch (device globals: allocation-free) ----------------
__device__ __nv_bfloat16 g_Qhi[BATCH * N_HEAD * SEQ * HD];
__device__ __nv_bfloat16 g_Qlo[BATCH * N_HEAD * SEQ * HD];
__device__ __nv_bfloat16 g_Khi[BATCH * N_HEAD * SEQ * HD];
__device__ __nv_bfloat16 g_Klo[BATCH * N_HEAD * SEQ * HD];
__device__ __nv_bfloat16 g_Vhi[BATCH * N_HEAD * SEQ * HD];
__device__ __nv_bfloat16 g_Vlo[BATCH * N_HEAD * SEQ * HD];

__device__ __half g_Xh[MTOT * C_EMBD];                 // x as fp16 (single)
__device__ __half g_Yh[MTOT * C_EMBD];                 // attn output as fp16
__device__ __half g_Wahi[3 * C_EMBD * C_EMBD];         // [N=3072][K=1024] fp16 hi
__device__ __half g_Walo[3 * C_EMBD * C_EMBD];         // fp16 lo residual
__device__ __half g_Wphi[C_EMBD * C_EMBD];             // [N=1024][K=1024]
__device__ __half g_Wplo[C_EMBD * C_EMBD];

// ---------------- helpers ----------------
__device__ __forceinline__ uint32_t smem_u32(const void* p) {
    uint32_t a;
    asm("{ .reg .u64 t; cvta.to.shared.u64 t, %1; cvt.u32.u64 %0, t; }" : "=r"(a) : "l"(p));
    return a;
}

__device__ __forceinline__ void ldsm_x4(uint32_t& r0, uint32_t& r1,
                                        uint32_t& r2, uint32_t& r3, uint32_t addr) {
    asm volatile("ldmatrix.sync.aligned.m8n8.x4.shared.b16 {%0,%1,%2,%3}, [%4];"
                 : "=r"(r0), "=r"(r1), "=r"(r2), "=r"(r3) : "r"(addr));
}

__device__ __forceinline__ void ldsm_x4_t(uint32_t& r0, uint32_t& r1,
                                          uint32_t& r2, uint32_t& r3, uint32_t addr) {
    asm volatile("ldmatrix.sync.aligned.m8n8.x4.trans.shared.b16 {%0,%1,%2,%3}, [%4];"
                 : "=r"(r0), "=r"(r1), "=r"(r2), "=r"(r3) : "r"(addr));
}

__device__ __forceinline__ void mma_bf16(float* c, const uint32_t* a, const uint32_t* b) {
    asm volatile(
        "mma.sync.aligned.m16n8k16.row.col.f32.bf16.bf16.f32 "
        "{%0,%1,%2,%3}, {%4,%5,%6,%7}, {%8,%9}, {%0,%1,%2,%3};"
        : "+f"(c[0]), "+f"(c[1]), "+f"(c[2]), "+f"(c[3])
        : "r"(a[0]), "r"(a[1]), "r"(a[2]), "r"(a[3]), "r"(b[0]), "r"(b[1]));
}

__device__ __forceinline__ void mma_f16(float* c, const uint32_t* a, const uint32_t* b) {
    asm volatile(
        "mma.sync.aligned.m16n8k16.row.col.f32.f16.f16.f32 "
        "{%0,%1,%2,%3}, {%4,%5,%6,%7}, {%8,%9}, {%0,%1,%2,%3};"
        : "+f"(c[0]), "+f"(c[1]), "+f"(c[2]), "+f"(c[3])
        : "r"(a[0]), "r"(a[1]), "r"(a[2]), "r"(a[3]), "r"(b[0]), "r"(b[1]));
}

__device__ __forceinline__ void cp_async16(uint32_t dst, const void* src) {
    asm volatile("cp.async.cg.shared.global [%0], [%1], 16;" :: "r"(dst), "l"(src));
}
__device__ __forceinline__ void cp_commit() {
    asm volatile("cp.async.commit_group;");
}
template <int N>
__device__ __forceinline__ void cp_wait() {
    asm volatile("cp.async.wait_group %0;" :: "n"(N));
}

// split two floats into bf16 hi pair + bf16 lo (residual) pair, packed b16x2
__device__ __forceinline__ void split2(float x, float y, uint32_t& hi, uint32_t& lo) {
    __nv_bfloat162 h = __floats2bfloat162_rn(x, y);
    __nv_bfloat162 l = __floats2bfloat162_rn(x - __bfloat162float(h.x),
                                             y - __bfloat162float(h.y));
    hi = *(uint32_t*)&h;
    lo = *(uint32_t*)&l;
}

// ---------------- prep kernels ----------------
__global__ __launch_bounds__(256)
void tofp16_kernel(const float* __restrict__ X) {
    int i = blockIdx.x * 256 + threadIdx.x;           // float4 index
    float4 v = ((const float4*)X)[i];
    ((__half2*)g_Xh)[2*i+0] = __floats2half2_rn(v.x, v.y);
    ((__half2*)g_Xh)[2*i+1] = __floats2half2_rn(v.z, v.w);
}

// transpose + split:  W[K, N] fp32  ->  Wt_hi/lo[N, K] fp16
__global__ __launch_bounds__(256)
void wsplit_kernel(const float* __restrict__ W, int which, int N) {
    __shared__ float t[32][33];
    __half* Hi = which ? g_Wphi : g_Wahi;
    __half* Lo = which ? g_Wplo : g_Walo;
    const int K = C_EMBD;
    int n0 = blockIdx.x * 32, k0 = blockIdx.y * 32;
    int tx = threadIdx.x, ty = threadIdx.y;
#pragma unroll
    for (int s = 0; s < 4; s++) {
        int i = ty + 8 * s;
        t[i][tx] = W[(size_t)(k0 + i) * N + n0 + tx];
    }
    __syncthreads();
#pragma unroll
    for (int s = 0; s < 4; s++) {
        int i = ty + 8 * s;
        float v = t[tx][i];                            // W[k0+tx][n0+i]
        __half h = __float2half_rn(v);
        Hi[(size_t)(n0 + i) * K + k0 + tx] = h;
        Lo[(size_t)(n0 + i) * K + k0 + tx] = __float2half_rn(v - __half2float(h));
    }
}

// ---------------- HMMA GEMM (fp16 2-pass: A single, W hi+lo) ----------------
// 512 threads, CTA tile 128x128, warp tile 32x32, cp.async 3-stage, BK=32.
#define BKC     32
#define NCHUNK  (C_EMBD / BKC)          // 32
#define ROWB    80                       // smem row pitch bytes
#define MATB    (128 * ROWB)             // 10240 B
#define STAGEB  (3 * MATB)               // 30720 B (A, Bh, Bl)
#define NSTAGE  3
#define A_OFF   0
#define BH_OFF  MATB
#define BL_OFF  (2 * MATB)

template <int MODE>   // 0: QKV gemm (split-scatter to Q/K/V hi/lo), 1: proj gemm
__global__ __launch_bounds__(512, 1)
void mma_gemm(const float* __restrict__ bias, float* __restrict__ Cout, int N)
{
    extern __shared__ char smem[];

    const __half* Ain = (MODE == 0) ? g_Xh : g_Yh;
    const __half* Bhi = (MODE == 0) ? g_Wahi : g_Wphi;
    const __half* Blo = (MODE == 0) ? g_Walo : g_Wplo;

    const int K = C_EMBD;
    int tid = threadIdx.x;
    int lane = tid & 31, wid = tid >> 5;
    int wm = wid & 3, wn = wid >> 2;                  // warp tile 32(M) x 32(N)
    int bn = blockIdx.x * 128;
    int bm = blockIdx.y * 128;

    uint32_t sb = smem_u32(smem);

    int r_ld = tid >> 2;                  // 0..127
    int q_ld = tid & 3;                   // 16B slot
    const __half* pA  = Ain + (size_t)(bm + r_ld) * K + q_ld * 8;
    const __half* pBh = Bhi + (size_t)(bn + r_ld) * K + q_ld * 8;
    const __half* pBl = Blo + (size_t)(bn + r_ld) * K + q_ld * 8;
    uint32_t stoff = (uint32_t)(r_ld * ROWB + q_ld * 16);

    uint32_t a_row = (uint32_t)(wm * 32 + (lane & 15));          // + mf*16
    uint32_t a_colb = (uint32_t)(((lane >> 4) << 3) * 2);        // + ks*32
    int bq = lane >> 3;
    uint32_t b_row = (uint32_t)(wn * 32 + ((bq >> 1) << 3) + (lane & 7));  // + nb*16
    uint32_t b_colb = (uint32_t)(((bq & 1) << 3) * 2);                     // + ks*32

    float acc[2][4][4];
#pragma unroll
    for (int i = 0; i < 2; i++)
#pragma unroll
        for (int j = 0; j < 4; j++)
#pragma unroll
            for (int k = 0; k < 4; k++) acc[i][j][k] = 0.0f;

    // prologue: stages 0,1
#pragma unroll
    for (int st = 0; st < 2; st++) {
        uint32_t d = sb + st * STAGEB + stoff;
        int k0 = st * BKC;
        cp_async16(d + A_OFF,  pA  + k0);
        cp_async16(d + BH_OFF, pBh + k0);
        cp_async16(d + BL_OFF, pBl + k0);
        cp_commit();
    }

    int stage_c = 0;
    int stage_l = 2;
    for (int ch = 0; ch < NCHUNK; ch++) {
        cp_wait<1>();
        __syncthreads();

        if (ch + 2 < NCHUNK) {
            uint32_t d = sb + stage_l * STAGEB + stoff;
            int k0 = (ch + 2) * BKC;
            cp_async16(d + A_OFF,  pA  + k0);
            cp_async16(d + BH_OFF, pBh + k0);
            cp_async16(d + BL_OFF, pBl + k0);
        }
        cp_commit();

        uint32_t stage = sb + stage_c * STAGEB;
#pragma unroll
        for (int ks = 0; ks < 2; ks++) {
            uint32_t kb = (uint32_t)(ks * 32);
            uint32_t a[2][4];
#pragma unroll
            for (int mf = 0; mf < 2; mf++) {
                uint32_t ra = stage + (a_row + mf * 16) * ROWB + a_colb + kb;
                ldsm_x4(a[mf][0], a[mf][1], a[mf][2], a[mf][3], ra + A_OFF);
            }
            uint32_t bh[4][2], bl[4][2];
#pragma unroll
            for (int nb = 0; nb < 2; nb++) {
                uint32_t rb = stage + (b_row + nb * 16) * ROWB + b_colb + kb;
                ldsm_x4(bh[2*nb][0], bh[2*nb][1], bh[2*nb+1][0], bh[2*nb+1][1], rb + BH_OFF);
                ldsm_x4(bl[2*nb][0], bl[2*nb][1], bl[2*nb+1][0], bl[2*nb+1][1], rb + BL_OFF);
            }
            // 2 passes, interleaved across 8 accumulators
#pragma unroll
            for (int mf = 0; mf < 2; mf++)
#pragma unroll
                for (int nf = 0; nf < 4; nf++)
                    mma_f16(acc[mf][nf], a[mf], bh[nf]);
#pragma unroll
            for (int mf = 0; mf < 2; mf++)
#pragma unroll
                for (int nf = 0; nf < 4; nf++)
                    mma_f16(acc[mf][nf], a[mf], bl[nf]);
        }

        stage_c = (stage_c == NSTAGE - 1) ? 0 : stage_c + 1;
        stage_l = (stage_l == NSTAGE - 1) ? 0 : stage_l + 1;
    }

    // epilogue: bias + write
#pragma unroll
    for (int mf = 0; mf < 2; mf++) {
#pragma unroll
        for (int nf = 0; nf < 4; nf++) {
            int m0 = bm + wm * 32 + mf * 16 + (lane >> 2);
            int n0 = bn + wn * 32 + nf * 8 + 2 * (lane & 3);
#pragma unroll
            for (int half = 0; half < 2; half++) {
                int m = m0 + half * 8;
                float v0 = acc[mf][nf][2 * half + 0] + bias[n0];
                float v1 = acc[mf][nf][2 * half + 1] + bias[n0 + 1];
                if (MODE == 0) {
                    int bb = m >> 11, t = m & 2047;
                    int which = n0 >> 10;
                    int cc = n0 & 1023;
                    int h = cc >> 6, d = cc & 63;
                    __nv_bfloat16* Hi = (which == 0) ? g_Qhi : (which == 1) ? g_Khi : g_Vhi;
                    __nv_bfloat16* Lo = (which == 0) ? g_Qlo : (which == 1) ? g_Klo : g_Vlo;
                    size_t idx = ((((size_t)bb * N_HEAD) + h) * SEQ + t) * HD + d;
                    __nv_bfloat16 h0 = __float2bfloat16(v0);
                    __nv_bfloat16 h1 = __float2bfloat16(v1);
                    *(__nv_bfloat162*)&Hi[idx] = __nv_bfloat162(h0, h1);
                    *(__nv_bfloat162*)&Lo[idx] = __nv_bfloat162(
                        __float2bfloat16(v0 - __bfloat162float(h0)),
                        __float2bfloat16(v1 - __bfloat162float(h1)));
                } else {
                    *(float2*)&Cout[(size_t)m * N + n0] = make_float2(v0, v1);
                }
            }
        }
    }
}

// ---------------------------------------------------------------------------
// HMMA flash attention: CTA = (b*h, 64-query block), 4 warps x 16 rows.
// bf16x3 (unchanged); epilogue writes Y as single fp16.
// ---------------------------------------------------------------------------
#define FPITCH 144    // smem row pitch (bytes)
#define FTILE  (64 * FPITCH)   // 9216 B

__global__ __launch_bounds__(128)
void flash_mma_kernel()
{
    extern __shared__ char fsm[];
    char* pQH = fsm;
    char* pKH = fsm + 2 * FTILE;
    char* pVH = fsm + 4 * FTILE;
    const uint32_t QH = smem_u32(pQH);
    const uint32_t KH = smem_u32(pKH);
    const uint32_t VH = smem_u32(pVH);

    int tid = threadIdx.x, lane = tid & 31, w = tid >> 5;
    int qb = (int)(gridDim.x - 1) - (int)blockIdx.x;    // heavy blocks first
    int bh = blockIdx.y;
    int q0 = qb * 64;
    size_t base = (size_t)bh * SEQ * HD;

    // load Q hi/lo tile
    {
        int r = tid >> 3, s = tid & 7;
#pragma unroll
        for (int it = 0; it < 4; it++) {
            int rr = r + it * 16;
            size_t off = base + (size_t)(q0 + rr) * HD + s * 8;
            *(uint4*)(pQH + rr * FPITCH + s * 16) = *(const uint4*)(g_Qhi + off);
            *(uint4*)(pQH + FTILE + rr * FPITCH + s * 16) = *(const uint4*)(g_Qlo + off);
        }
    }

    float m0 = -1e30f, m1 = -1e30f, l0 = 0.0f, l1 = 0.0f;
    float O[8][4];
#pragma unroll
    for (int i = 0; i < 8; i++)
#pragma unroll
        for (int j = 0; j < 4; j++) O[i][j] = 0.0f;

    for (int kb = 0; kb <= qb; kb++) {
        __syncthreads();
        int k0 = kb * 64;
        {
            int r = tid >> 3, s = tid & 7;
#pragma unroll
            for (int it = 0; it < 4; it++) {
                int rr = r + it * 16;
                size_t off = base + (size_t)(k0 + rr) * HD + s * 8;
                *(uint4*)(pKH + rr * FPITCH + s * 16) = *(const uint4*)(g_Khi + off);
                *(uint4*)(pKH + FTILE + rr * FPITCH + s * 16) = *(const uint4*)(g_Klo + off);
                *(uint4*)(pVH + rr * FPITCH + s * 16) = *(const uint4*)(g_Vhi + off);
                *(uint4*)(pVH + FTILE + rr * FPITCH + s * 16) = *(const uint4*)(g_Vlo + off);
            }
        }
        __syncthreads();

        // ---- S = Q K^T (bf16x3, pass-interleaved) ----
        float S[8][4];
#pragma unroll
        for (int i = 0; i < 8; i++)
#pragma unroll
            for (int j = 0; j < 4; j++) S[i][j] = 0.0f;

        int bq = lane >> 3;
#pragma unroll
        for (int s = 0; s < 4; s++) {
            uint32_t ah[4], al[4];
            uint32_t ra = QH + (w * 16 + (lane & 15)) * FPITCH + (lane >> 4) * 16 + s * 32;
            ldsm_x4(ah[0], ah[1], ah[2], ah[3], ra);
            ldsm_x4(al[0], al[1], al[2], al[3], ra + FTILE);
            uint32_t bh_[4][4], bl_[4][4];
#pragma unroll
            for (int nt = 0; nt < 4; nt++) {
                uint32_t rb = KH + (nt * 16 + ((bq >> 1) << 3) + (lane & 7)) * FPITCH
                            + (bq & 1) * 16 + s * 32;
                ldsm_x4(bh_[nt][0], bh_[nt][1], bh_[nt][2], bh_[nt][3], rb);
                ldsm_x4(bl_[nt][0], bl_[nt][1], bl_[nt][2], bl_[nt][3], rb + FTILE);
            }
#pragma unroll
            for (int nt = 0; nt < 4; nt++) {
                mma_bf16(S[2*nt],   ah, &bh_[nt][0]);
                mma_bf16(S[2*nt+1], ah, &bh_[nt][2]);
            }
#pragma unroll
            for (int nt = 0; nt < 4; nt++) {
                mma_bf16(S[2*nt],   ah, &bl_[nt][0]);
                mma_bf16(S[2*nt+1], ah, &bl_[nt][2]);
            }
#pragma unroll
            for (int nt = 0; nt < 4; nt++) {
                mma_bf16(S[2*nt],   al, &bh_[nt][0]);
                mma_bf16(S[2*nt+1], al, &bh_[nt][2]);
            }
        }

        // ---- scale + causal mask ----
#pragma unroll
        for (int nb = 0; nb < 8; nb++)
#pragma unroll
            for (int e = 0; e < 4; e++) S[nb][e] *= 0.125f;

        if (kb == qb) {
            int rl0 = w * 16 + (lane >> 2);
#pragma unroll
            for (int nb = 0; nb < 8; nb++) {
                int c = nb * 8 + 2 * (lane & 3);
                if (c     > rl0)     S[nb][0] = -1e30f;
                if (c + 1 > rl0)     S[nb][1] = -1e30f;
                if (c     > rl0 + 8) S[nb][2] = -1e30f;
                if (c + 1 > rl0 + 8) S[nb][3] = -1e30f;
            }
        }

        // ---- online softmax ----
        float mx0 = -1e30f, mx1 = -1e30f;
#pragma unroll
        for (int nb = 0; nb < 8; nb++) {
            mx0 = fmaxf(mx0, fmaxf(S[nb][0], S[nb][1]));
            mx1 = fmaxf(mx1, fmaxf(S[nb][2], S[nb][3]));
        }
        mx0 = fmaxf(mx0, __shfl_xor_sync(0xffffffffu, mx0, 1));
        mx0 = fmaxf(mx0, __shfl_xor_sync(0xffffffffu, mx0, 2));
        mx1 = fmaxf(mx1, __shfl_xor_sync(0xffffffffu, mx1, 1));
        mx1 = fmaxf(mx1, __shfl_xor_sync(0xffffffffu, mx1, 2));
        float mn0 = fmaxf(m0, mx0), mn1 = fmaxf(m1, mx1);
        float corr0 = __expf(m0 - mn0), corr1 = __expf(m1 - mn1);
        float s0 = 0.0f, s1 = 0.0f;
#pragma unroll
        for (int nb = 0; nb < 8; nb++) {
            S[nb][0] = __expf(S[nb][0] - mn0); s0 += S[nb][0];
            S[nb][1] = __expf(S[nb][1] - mn0); s0 += S[nb][1];
            S[nb][2] = __expf(S[nb][2] - mn1); s1 += S[nb][2];
            S[nb][3] = __expf(S[nb][3] - mn1); s1 += S[nb][3];
        }
        s0 += __shfl_xor_sync(0xffffffffu, s0, 1);
        s0 += __shfl_xor_sync(0xffffffffu, s0, 2);
        s1 += __shfl_xor_sync(0xffffffffu, s1, 1);
        s1 += __shfl_xor_sync(0xffffffffu, s1, 2);
        l0 = l0 * corr0 + s0;
        l1 = l1 * corr1 + s1;
        m0 = mn0; m1 = mn1;
#pragma unroll
        for (int nb = 0; nb < 8; nb++) {
            O[nb][0] *= corr0; O[nb][1] *= corr0;
            O[nb][2] *= corr1; O[nb][3] *= corr1;
        }

        // ---- O += P V (bf16x3, pass-interleaved) ----
#pragma unroll
        for (int s = 0; s < 4; s++) {
            uint32_t pa_h[4], pa_l[4];
            split2(S[2*s][0],   S[2*s][1],   pa_h[0], pa_l[0]);
            split2(S[2*s][2],   S[2*s][3],   pa_h[1], pa_l[1]);
            split2(S[2*s+1][0], S[2*s+1][1], pa_h[2], pa_l[2]);
            split2(S[2*s+1][2], S[2*s+1][3], pa_h[3], pa_l[3]);
            uint32_t vh[4][4], vl[4][4];
#pragma unroll
            for (int nt = 0; nt < 4; nt++) {
                uint32_t rv = VH + (s * 16 + (lane & 7) + ((lane >> 3) & 1) * 8) * FPITCH
                            + nt * 32 + (lane >> 4) * 16;
                ldsm_x4_t(vh[nt][0], vh[nt][1], vh[nt][2], vh[nt][3], rv);
                ldsm_x4_t(vl[nt][0], vl[nt][1], vl[nt][2], vl[nt][3], rv + FTILE);
            }
#pragma unroll
            for (int nt = 0; nt < 4; nt++) {
                mma_bf16(O[2*nt],   pa_h, &vh[nt][0]);
                mma_bf16(O[2*nt+1], pa_h, &vh[nt][2]);
            }
#pragma unroll
            for (int nt = 0; nt < 4; nt++) {
                mma_bf16(O[2*nt],   pa_h, &vl[nt][0]);
                mma_bf16(O[2*nt+1], pa_h, &vl[nt][2]);
            }
#pragma unroll
            for (int nt = 0; nt < 4; nt++) {
                mma_bf16(O[2*nt],   pa_l, &vh[nt][0]);
                mma_bf16(O[2*nt+1], pa_l, &vh[nt][2]);
            }
        }
    }

    // ---- normalize + write Y (single fp16, [B,T,C]) ----
    int b = bh >> 4, h = bh & 15;
    int r0g = q0 + w * 16 + (lane >> 2);
    int dcol = 2 * (lane & 3);
    float inv0 = 1.0f / l0, inv1 = 1.0f / l1;
#pragma unroll
    for (int nb = 0; nb < 8; nb++) {
        int d = nb * 8 + dcol;
        {
            size_t idx = ((size_t)(b * SEQ + r0g)) * C_EMBD + h * HD + d;
            *(__half2*)&g_Yh[idx] = __floats2half2_rn(O[nb][0] * inv0, O[nb][1] * inv0);
        }
        {
            size_t idx = ((size_t)(b * SEQ + r0g + 8)) * C_EMBD + h * HD + d;
            *(__half2*)&g_Yh[idx] = __floats2half2_rn(O[nb][2] * inv1, O[nb][3] * inv1);
        }
    }
}

// ---------------------------------------------------------------------------
extern "C" void kernel_launch(void* const* d_in, const int* in_sizes, int n_in,
                              void* d_out, int out_size)
{
    const float* x      = (const float*)d_in[0];
    const float* W_attn = (const float*)d_in[1];
    const float* b_attn = (const float*)d_in[2];
    const float* W_proj = (const float*)d_in[3];
    const float* b_proj = (const float*)d_in[4];
    float* out = (float*)d_out;

    (void)in_sizes; (void)n_in; (void)out_size;

    static const int FLASH_SMEM = 6 * FTILE;                        // 55296 B
    static const int GEMM_SMEM  = NSTAGE * STAGEB;                  // 92160 B
    cudaFuncSetAttribute(flash_mma_kernel,
                         cudaFuncAttributeMaxDynamicSharedMemorySize, FLASH_SMEM);
    cudaFuncSetAttribute(mma_gemm<0>,
                         cudaFuncAttributeMaxDynamicSharedMemorySize, GEMM_SMEM);
    cudaFuncSetAttribute(mma_gemm<1>,
                         cudaFuncAttributeMaxDynamicSharedMemorySize, GEMM_SMEM);

    // 0) prep: x -> fp16; transpose+split weights -> fp16 hi/lo
    tofp16_kernel<<<MTOT * C_EMBD / 4 / 256, 256>>>(x);
    wsplit_kernel<<<dim3(3 * C_EMBD / 32, C_EMBD / 32), dim3(32, 8)>>>(W_attn, 0, 3 * C_EMBD);
    wsplit_kernel<<<dim3(C_EMBD / 32, C_EMBD / 32), dim3(32, 8)>>>(W_proj, 1, C_EMBD);

    // 1) QKV GEMM (fp16 2-pass) + bias -> Q/K/V bf16 hi/lo [B,H,T,hd]
    mma_gemm<0><<<dim3(3 * C_EMBD / 128, MTOT / 128), 512, GEMM_SMEM>>>(
        b_attn, nullptr, 3 * C_EMBD);

    // 2) causal flash attention (bf16x3) -> Y fp16
    flash_mma_kernel<<<dim3(SEQ / 64, BATCH * N_HEAD), 128, FLASH_SMEM>>>();

    // 3) output projection (fp16 2-pass) + bias -> d_out
    mma_gemm<1><<<dim3(C_EMBD / 128, MTOT / 128), 512, GEMM_SMEM>>>(
        b_proj, out, C_EMBD);
}

// round 10
// speedup vs baseline: 1.3839x; 1.1073x over previous
#include <cuda_runtime.h>
#include <cuda_bf16.h>
#include <cuda_fp16.h>
#include <cstdint>

#define N_HEAD 16
#define C_EMBD 1024
#define HD     64
#define BATCH  4
#define SEQ    2048
#define MTOT   (BATCH * SEQ)   // 8192

// ---------------- scratch (device globals: allocation-free) ----------------
__device__ __half g_Qh [BATCH * N_HEAD * SEQ * HD];    // Q single fp16
__device__ __half g_Khi[BATCH * N_HEAD * SEQ * HD];    // K fp16 hi
__device__ __half g_Klo[BATCH * N_HEAD * SEQ * HD];    // K fp16 lo
__device__ __half g_Vhi[BATCH * N_HEAD * SEQ * HD];    // V fp16 hi
__device__ __half g_Vlo[BATCH * N_HEAD * SEQ * HD];    // V fp16 lo

__device__ __half g_Xh[MTOT * C_EMBD];                 // x as fp16 (single)
__device__ __half g_Yh[MTOT * C_EMBD];                 // attn output as fp16
__device__ __half g_Wahi[3 * C_EMBD * C_EMBD];         // [N=3072][K=1024] fp16 hi
__device__ __half g_Walo[3 * C_EMBD * C_EMBD];         // fp16 lo residual
__device__ __half g_Wphi[C_EMBD * C_EMBD];             // [N=1024][K=1024]
__device__ __half g_Wplo[C_EMBD * C_EMBD];

// ---------------- helpers ----------------
__device__ __forceinline__ uint32_t smem_u32(const void* p) {
    uint32_t a;
    asm("{ .reg .u64 t; cvta.to.shared.u64 t, %1; cvt.u32.u64 %0, t; }" : "=r"(a) : "l"(p));
    return a;
}

__device__ __forceinline__ void ldsm_x4(uint32_t& r0, uint32_t& r1,
                                        uint32_t& r2, uint32_t& r3, uint32_t addr) {
    asm volatile("ldmatrix.sync.aligned.m8n8.x4.shared.b16 {%0,%1,%2,%3}, [%4];"
                 : "=r"(r0), "=r"(r1), "=r"(r2), "=r"(r3) : "r"(addr));
}

__device__ __forceinline__ void ldsm_x4_t(uint32_t& r0, uint32_t& r1,
                                          uint32_t& r2, uint32_t& r3, uint32_t addr) {
    asm volatile("ldmatrix.sync.aligned.m8n8.x4.trans.shared.b16 {%0,%1,%2,%3}, [%4];"
                 : "=r"(r0), "=r"(r1), "=r"(r2), "=r"(r3) : "r"(addr));
}

__device__ __forceinline__ void mma_f16(float* c, const uint32_t* a, const uint32_t* b) {
    asm volatile(
        "mma.sync.aligned.m16n8k16.row.col.f32.f16.f16.f32 "
        "{%0,%1,%2,%3}, {%4,%5,%6,%7}, {%8,%9}, {%0,%1,%2,%3};"
        : "+f"(c[0]), "+f"(c[1]), "+f"(c[2]), "+f"(c[3])
        : "r"(a[0]), "r"(a[1]), "r"(a[2]), "r"(a[3]), "r"(b[0]), "r"(b[1]));
}

__device__ __forceinline__ void cp_async16(uint32_t dst, const void* src) {
    asm volatile("cp.async.cg.shared.global [%0], [%1], 16;" :: "r"(dst), "l"(src));
}
__device__ __forceinline__ void cp_commit() {
    asm volatile("cp.async.commit_group;");
}
template <int N>
__device__ __forceinline__ void cp_wait() {
    asm volatile("cp.async.wait_group %0;" :: "n"(N));
}

// ---------------- prep kernels ----------------
__global__ __launch_bounds__(256)
void tofp16_kernel(const float* __restrict__ X) {
    int i = blockIdx.x * 256 + threadIdx.x;           // float4 index
    float4 v = ((const float4*)X)[i];
    ((__half2*)g_Xh)[2*i+0] = __floats2half2_rn(v.x, v.y);
    ((__half2*)g_Xh)[2*i+1] = __floats2half2_rn(v.z, v.w);
}

// transpose + split:  W[K, N] fp32  ->  Wt_hi/lo[N, K] fp16
__global__ __launch_bounds__(256)
void wsplit_kernel(const float* __restrict__ W, int which, int N) {
    __shared__ float t[32][33];
    __half* Hi = which ? g_Wphi : g_Wahi;
    __half* Lo = which ? g_Wplo : g_Walo;
    const int K = C_EMBD;
    int n0 = blockIdx.x * 32, k0 = blockIdx.y * 32;
    int tx = threadIdx.x, ty = threadIdx.y;
#pragma unroll
    for (int s = 0; s < 4; s++) {
        int i = ty + 8 * s;
        t[i][tx] = W[(size_t)(k0 + i) * N + n0 + tx];
    }
    __syncthreads();
#pragma unroll
    for (int s = 0; s < 4; s++) {
        int i = ty + 8 * s;
        float v = t[tx][i];                            // W[k0+tx][n0+i]
        __half h = __float2half_rn(v);
        Hi[(size_t)(n0 + i) * K + k0 + tx] = h;
        Lo[(size_t)(n0 + i) * K + k0 + tx] = __float2half_rn(v - __half2float(h));
    }
}

// ---------------- HMMA GEMM (fp16 2-pass: A single, W hi+lo) ----------------
// 512 threads, CTA tile 128x128, warp tile 32x32, cp.async 3-stage, BK=32.
#define BKC     32
#define NCHUNK  (C_EMBD / BKC)          // 32
#define ROWB    80                       // smem row pitch bytes
#define MATB    (128 * ROWB)             // 10240 B
#define STAGEB  (3 * MATB)               // 30720 B (A, Bh, Bl)
#define NSTAGE  3
#define A_OFF   0
#define BH_OFF  MATB
#define BL_OFF  (2 * MATB)

template <int MODE>   // 0: QKV gemm (scatter to Q single / K,V hi+lo), 1: proj gemm
__global__ __launch_bounds__(512, 1)
void mma_gemm(const float* __restrict__ bias, float* __restrict__ Cout, int N)
{
    extern __shared__ char smem[];

    const __half* Ain = (MODE == 0) ? g_Xh : g_Yh;
    const __half* Bhi = (MODE == 0) ? g_Wahi : g_Wphi;
    const __half* Blo = (MODE == 0) ? g_Walo : g_Wplo;

    const int K = C_EMBD;
    int tid = threadIdx.x;
    int lane = tid & 31, wid = tid >> 5;
    int wm = wid & 3, wn = wid >> 2;                  // warp tile 32(M) x 32(N)
    int bn = blockIdx.x * 128;
    int bm = blockIdx.y * 128;

    uint32_t sb = smem_u32(smem);

    int r_ld = tid >> 2;                  // 0..127
    int q_ld = tid & 3;                   // 16B slot
    const __half* pA  = Ain + (size_t)(bm + r_ld) * K + q_ld * 8;
    const __half* pBh = Bhi + (size_t)(bn + r_ld) * K + q_ld * 8;
    const __half* pBl = Blo + (size_t)(bn + r_ld) * K + q_ld * 8;
    uint32_t stoff = (uint32_t)(r_ld * ROWB + q_ld * 16);

    uint32_t a_row = (uint32_t)(wm * 32 + (lane & 15));          // + mf*16
    uint32_t a_colb = (uint32_t)(((lane >> 4) << 3) * 2);        // + ks*32
    int bq = lane >> 3;
    uint32_t b_row = (uint32_t)(wn * 32 + ((bq >> 1) << 3) + (lane & 7));  // + nb*16
    uint32_t b_colb = (uint32_t)(((bq & 1) << 3) * 2);                     // + ks*32

    float acc[2][4][4];
#pragma unroll
    for (int i = 0; i < 2; i++)
#pragma unroll
        for (int j = 0; j < 4; j++)
#pragma unroll
            for (int k = 0; k < 4; k++) acc[i][j][k] = 0.0f;

    // prologue: stages 0,1
#pragma unroll
    for (int st = 0; st < 2; st++) {
        uint32_t d = sb + st * STAGEB + stoff;
        int k0 = st * BKC;
        cp_async16(d + A_OFF,  pA  + k0);
        cp_async16(d + BH_OFF, pBh + k0);
        cp_async16(d + BL_OFF, pBl + k0);
        cp_commit();
    }

    int stage_c = 0;
    int stage_l = 2;
    for (int ch = 0; ch < NCHUNK; ch++) {
        cp_wait<1>();
        __syncthreads();

        if (ch + 2 < NCHUNK) {
            uint32_t d = sb + stage_l * STAGEB + stoff;
            int k0 = (ch + 2) * BKC;
            cp_async16(d + A_OFF,  pA  + k0);
            cp_async16(d + BH_OFF, pBh + k0);
            cp_async16(d + BL_OFF, pBl + k0);
        }
        cp_commit();

        uint32_t stage = sb + stage_c * STAGEB;
#pragma unroll
        for (int ks = 0; ks < 2; ks++) {
            uint32_t kb = (uint32_t)(ks * 32);
            uint32_t a[2][4];
#pragma unroll
            for (int mf = 0; mf < 2; mf++) {
                uint32_t ra = stage + (a_row + mf * 16) * ROWB + a_colb + kb;
                ldsm_x4(a[mf][0], a[mf][1], a[mf][2], a[mf][3], ra + A_OFF);
            }
            uint32_t bh[4][2], bl[4][2];
#pragma unroll
            for (int nb = 0; nb < 2; nb++) {
                uint32_t rb = stage + (b_row + nb * 16) * ROWB + b_colb + kb;
                ldsm_x4(bh[2*nb][0], bh[2*nb][1], bh[2*nb+1][0], bh[2*nb+1][1], rb + BH_OFF);
                ldsm_x4(bl[2*nb][0], bl[2*nb][1], bl[2*nb+1][0], bl[2*nb+1][1], rb + BL_OFF);
            }
            // 2 passes, interleaved across 8 accumulators
#pragma unroll
            for (int mf = 0; mf < 2; mf++)
#pragma unroll
                for (int nf = 0; nf < 4; nf++)
                    mma_f16(acc[mf][nf], a[mf], bh[nf]);
#pragma unroll
            for (int mf = 0; mf < 2; mf++)
#pragma unroll
                for (int nf = 0; nf < 4; nf++)
                    mma_f16(acc[mf][nf], a[mf], bl[nf]);
        }

        stage_c = (stage_c == NSTAGE - 1) ? 0 : stage_c + 1;
        stage_l = (stage_l == NSTAGE - 1) ? 0 : stage_l + 1;
    }

    // epilogue: bias + write
#pragma unroll
    for (int mf = 0; mf < 2; mf++) {
#pragma unroll
        for (int nf = 0; nf < 4; nf++) {
            int m0 = bm + wm * 32 + mf * 16 + (lane >> 2);
            int n0 = bn + wn * 32 + nf * 8 + 2 * (lane & 3);
#pragma unroll
            for (int half = 0; half < 2; half++) {
                int m = m0 + half * 8;
                float v0 = acc[mf][nf][2 * half + 0] + bias[n0];
                float v1 = acc[mf][nf][2 * half + 1] + bias[n0 + 1];
                if (MODE == 0) {
                    int bb = m >> 11, t = m & 2047;
                    int which = n0 >> 10;
                    int cc = n0 & 1023;
                    int h = cc >> 6, d = cc & 63;
                    size_t idx = ((((size_t)bb * N_HEAD) + h) * SEQ + t) * HD + d;
                    if (which == 0) {
                        *(__half2*)&g_Qh[idx] = __floats2half2_rn(v0, v1);
                    } else {
                        __half* Hi = (which == 1) ? g_Khi : g_Vhi;
                        __half* Lo = (which == 1) ? g_Klo : g_Vlo;
                        __half h0 = __float2half_rn(v0);
                        __half h1 = __float2half_rn(v1);
                        *(__half2*)&Hi[idx] = __halves2half2(h0, h1);
                        *(__half2*)&Lo[idx] = __floats2half2_rn(
                            v0 - __half2float(h0), v1 - __half2float(h1));
                    }
                } else {
                    *(float2*)&Cout[(size_t)m * N + n0] = make_float2(v0, v1);
                }
            }
        }
    }
}

// ---------------------------------------------------------------------------
// HMMA flash attention: CTA = (b*h, 64-query block), 4 warps x 16 rows.
// fp16 4-pass: S = Qh*(Khi+Klo), PV = Ph*(Vhi+Vlo). Softmax in registers.
// ---------------------------------------------------------------------------
#define FPITCH 144    // smem row pitch (bytes)
#define FTILE  (64 * FPITCH)   // 9216 B

__global__ __launch_bounds__(128)
void flash_mma_kernel()
{
    extern __shared__ char fsm[];
    char* pQ  = fsm;                    // 1 tile  (Q single fp16)
    char* pKH = fsm + 1 * FTILE;        // 2 tiles (K hi, K lo)
    char* pVH = fsm + 3 * FTILE;        // 2 tiles (V hi, V lo)
    const uint32_t Qs = smem_u32(pQ);
    const uint32_t KH = smem_u32(pKH);
    const uint32_t VH = smem_u32(pVH);

    int tid = threadIdx.x, lane = tid & 31, w = tid >> 5;
    int qb = (int)(gridDim.x - 1) - (int)blockIdx.x;    // heavy blocks first
    int bh = blockIdx.y;
    int q0 = qb * 64;
    size_t base = (size_t)bh * SEQ * HD;

    // load Q tile (single fp16)
    {
        int r = tid >> 3, s = tid & 7;
#pragma unroll
        for (int it = 0; it < 4; it++) {
            int rr = r + it * 16;
            size_t off = base + (size_t)(q0 + rr) * HD + s * 8;
            *(uint4*)(pQ + rr * FPITCH + s * 16) = *(const uint4*)(g_Qh + off);
        }
    }

    float m0 = -1e30f, m1 = -1e30f, l0 = 0.0f, l1 = 0.0f;
    float O[8][4];
#pragma unroll
    for (int i = 0; i < 8; i++)
#pragma unroll
        for (int j = 0; j < 4; j++) O[i][j] = 0.0f;

    for (int kb = 0; kb <= qb; kb++) {
        __syncthreads();
        int k0 = kb * 64;
        {
            int r = tid >> 3, s = tid & 7;
#pragma unroll
            for (int it = 0; it < 4; it++) {
                int rr = r + it * 16;
                size_t off = base + (size_t)(k0 + rr) * HD + s * 8;
                *(uint4*)(pKH + rr * FPITCH + s * 16) = *(const uint4*)(g_Khi + off);
                *(uint4*)(pKH + FTILE + rr * FPITCH + s * 16) = *(const uint4*)(g_Klo + off);
                *(uint4*)(pVH + rr * FPITCH + s * 16) = *(const uint4*)(g_Vhi + off);
                *(uint4*)(pVH + FTILE + rr * FPITCH + s * 16) = *(const uint4*)(g_Vlo + off);
            }
        }
        __syncthreads();

        // ---- S = Q K^T (fp16 2-pass, interleaved) ----
        float S[8][4];
#pragma unroll
        for (int i = 0; i < 8; i++)
#pragma unroll
            for (int j = 0; j < 4; j++) S[i][j] = 0.0f;

        int bq = lane >> 3;
#pragma unroll
        for (int s = 0; s < 4; s++) {
            uint32_t a[4];
            uint32_t ra = Qs + (w * 16 + (lane & 15)) * FPITCH + (lane >> 4) * 16 + s * 32;
            ldsm_x4(a[0], a[1], a[2], a[3], ra);
            uint32_t bh_[4][4], bl_[4][4];
#pragma unroll
            for (int nt = 0; nt < 4; nt++) {
                uint32_t rb = KH + (nt * 16 + ((bq >> 1) << 3) + (lane & 7)) * FPITCH
                            + (bq & 1) * 16 + s * 32;
                ldsm_x4(bh_[nt][0], bh_[nt][1], bh_[nt][2], bh_[nt][3], rb);
                ldsm_x4(bl_[nt][0], bl_[nt][1], bl_[nt][2], bl_[nt][3], rb + FTILE);
            }
#pragma unroll
            for (int nt = 0; nt < 4; nt++) {
                mma_f16(S[2*nt],   a, &bh_[nt][0]);
                mma_f16(S[2*nt+1], a, &bh_[nt][2]);
            }
#pragma unroll
            for (int nt = 0; nt < 4; nt++) {
                mma_f16(S[2*nt],   a, &bl_[nt][0]);
                mma_f16(S[2*nt+1], a, &bl_[nt][2]);
            }
        }

        // ---- scale + causal mask ----
#pragma unroll
        for (int nb = 0; nb < 8; nb++)
#pragma unroll
            for (int e = 0; e < 4; e++) S[nb][e] *= 0.125f;

        if (kb == qb) {
            int rl0 = w * 16 + (lane >> 2);
#pragma unroll
            for (int nb = 0; nb < 8; nb++) {
                int c = nb * 8 + 2 * (lane & 3);
                if (c     > rl0)     S[nb][0] = -1e30f;
                if (c + 1 > rl0)     S[nb][1] = -1e30f;
                if (c     > rl0 + 8) S[nb][2] = -1e30f;
                if (c + 1 > rl0 + 8) S[nb][3] = -1e30f;
            }
        }

        // ---- online softmax ----
        float mx0 = -1e30f, mx1 = -1e30f;
#pragma unroll
        for (int nb = 0; nb < 8; nb++) {
            mx0 = fmaxf(mx0, fmaxf(S[nb][0], S[nb][1]));
            mx1 = fmaxf(mx1, fmaxf(S[nb][2], S[nb][3]));
        }
        mx0 = fmaxf(mx0, __shfl_xor_sync(0xffffffffu, mx0, 1));
        mx0 = fmaxf(mx0, __shfl_xor_sync(0xffffffffu, mx0, 2));
        mx1 = fmaxf(mx1, __shfl_xor_sync(0xffffffffu, mx1, 1));
        mx1 = fmaxf(mx1, __shfl_xor_sync(0xffffffffu, mx1, 2));
        float mn0 = fmaxf(m0, mx0), mn1 = fmaxf(m1, mx1);
        float corr0 = __expf(m0 - mn0), corr1 = __expf(m1 - mn1);
        float s0 = 0.0f, s1 = 0.0f;
#pragma unroll
        for (int nb = 0; nb < 8; nb++) {
            S[nb][0] = __expf(S[nb][0] - mn0); s0 += S[nb][0];
            S[nb][1] = __expf(S[nb][1] - mn0); s0 += S[nb][1];
            S[nb][2] = __expf(S[nb][2] - mn1); s1 += S[nb][2];
            S[nb][3] = __expf(S[nb][3] - mn1); s1 += S[nb][3];
        }
        s0 += __shfl_xor_sync(0xffffffffu, s0, 1);
        s0 += __shfl_xor_sync(0xffffffffu, s0, 2);
        s1 += __shfl_xor_sync(0xffffffffu, s1, 1);
        s1 += __shfl_xor_sync(0xffffffffu, s1, 2);
        l0 = l0 * corr0 + s0;
        l1 = l1 * corr1 + s1;
        m0 = mn0; m1 = mn1;
#pragma unroll
        for (int nb = 0; nb < 8; nb++) {
            O[nb][0] *= corr0; O[nb][1] *= corr0;
            O[nb][2] *= corr1; O[nb][3] *= corr1;
        }

        // ---- O += P V (fp16 2-pass, P packed single fp16) ----
#pragma unroll
        for (int s = 0; s < 4; s++) {
            uint32_t pa[4];
            pa[0] = *(uint32_t*)&(__half2&)*(__half2[]){__floats2half2_rn(S[2*s][0],   S[2*s][1])};
            // (packing done explicitly below to avoid compound literal issues)
            __half2 p0 = __floats2half2_rn(S[2*s][0],   S[2*s][1]);
            __half2 p1 = __floats2half2_rn(S[2*s][2],   S[2*s][3]);
            __half2 p2 = __floats2half2_rn(S[2*s+1][0], S[2*s+1][1]);
            __half2 p3 = __floats2half2_rn(S[2*s+1][2], S[2*s+1][3]);
            pa[0] = *(uint32_t*)&p0;
            pa[1] = *(uint32_t*)&p1;
            pa[2] = *(uint32_t*)&p2;
            pa[3] = *(uint32_t*)&p3;
            uint32_t vh[4][4], vl[4][4];
#pragma unroll
            for (int nt = 0; nt < 4; nt++) {
                uint32_t rv = VH + (s * 16 + (lane & 7) + ((lane >> 3) & 1) * 8) * FPITCH
                            + nt * 32 + (lane >> 4) * 16;
                ldsm_x4_t(vh[nt][0], vh[nt][1], vh[nt][2], vh[nt][3], rv);
                ldsm_x4_t(vl[nt][0], vl[nt][1], vl[nt][2], vl[nt][3], rv + FTILE);
            }
#pragma unroll
            for (int nt = 0; nt < 4; nt++) {
                mma_f16(O[2*nt],   pa, &vh[nt][0]);
                mma_f16(O[2*nt+1], pa, &vh[nt][2]);
            }
#pragma unroll
            for (int nt = 0; nt < 4; nt++) {
                mma_f16(O[2*nt],   pa, &vl[nt][0]);
                mma_f16(O[2*nt+1], pa, &vl[nt][2]);
            }
        }
    }

    // ---- normalize + write Y (single fp16, [B,T,C]) ----
    int b = bh >> 4, h = bh & 15;
    int r0g = q0 + w * 16 + (lane >> 2);
    int dcol = 2 * (lane & 3);
    float inv0 = 1.0f / l0, inv1 = 1.0f / l1;
#pragma unroll
    for (int nb = 0; nb < 8; nb++) {
        int d = nb * 8 + dcol;
        {
            size_t idx = ((size_t)(b * SEQ + r0g)) * C_EMBD + h * HD + d;
            *(__half2*)&g_Yh[idx] = __floats2half2_rn(O[nb][0] * inv0, O[nb][1] * inv0);
        }
        {
            size_t idx = ((size_t)(b * SEQ + r0g + 8)) * C_EMBD + h * HD + d;
            *(__half2*)&g_Yh[idx] = __floats2half2_rn(O[nb][2] * inv1, O[nb][3] * inv1);
        }
    }
}

// ---------------------------------------------------------------------------
extern "C" void kernel_launch(void* const* d_in, const int* in_sizes, int n_in,
                              void* d_out, int out_size)
{
    const float* x      = (const float*)d_in[0];
    const float* W_attn = (const float*)d_in[1];
    const float* b_attn = (const float*)d_in[2];
    const float* W_proj = (const float*)d_in[3];
    const float* b_proj = (const float*)d_in[4];
    float* out = (float*)d_out;

    (void)in_sizes; (void)n_in; (void)out_size;

    static const int FLASH_SMEM = 5 * FTILE;                        // 46080 B
    static const int GEMM_SMEM  = NSTAGE * STAGEB;                  // 92160 B
    cudaFuncSetAttribute(flash_mma_kernel,
                         cudaFuncAttributeMaxDynamicSharedMemorySize, FLASH_SMEM);
    cudaFuncSetAttribute(mma_gemm<0>,
                         cudaFuncAttributeMaxDynamicSharedMemorySize, GEMM_SMEM);
    cudaFuncSetAttribute(mma_gemm<1>,
                         cudaFuncAttributeMaxDynamicSharedMemorySize, GEMM_SMEM);

    // 0) prep: x -> fp16; transpose+split weights -> fp16 hi/lo
    tofp16_kernel<<<MTOT * C_EMBD / 4 / 256, 256>>>(x);
    wsplit_kernel<<<dim3(3 * C_EMBD / 32, C_EMBD / 32), dim3(32, 8)>>>(W_attn, 0, 3 * C_EMBD);
    wsplit_kernel<<<dim3(C_EMBD / 32, C_EMBD / 32), dim3(32, 8)>>>(W_proj, 1, C_EMBD);

    // 1) QKV GEMM (fp16 2-pass) + bias -> Q single fp16, K/V fp16 hi+lo [B,H,T,hd]
    mma_gemm<0><<<dim3(3 * C_EMBD / 128, MTOT / 128), 512, GEMM_SMEM>>>(
        b_attn, nullptr, 3 * C_EMBD);

    // 2) causal flash attention (fp16 4-pass) -> Y fp16
    flash_mma_kernel<<<dim3(SEQ / 64, BATCH * N_HEAD), 128, FLASH_SMEM>>>();

    // 3) output projection (fp16 2-pass) + bias -> d_out
    mma_gemm<1><<<dim3(C_EMBD / 128, MTOT / 128), 512, GEMM_SMEM>>>(
        b_proj, out, C_EMBD);
}

// round 11
// speedup vs baseline: 1.7962x; 1.2979x over previous
#include <cuda_runtime.h>
#include <cuda_bf16.h>
#include <cuda_fp16.h>
#include <cstdint>

#define N_HEAD 16
#define C_EMBD 1024
#define HD     64
#define BATCH  4
#define SEQ    2048
#define MTOT   (BATCH * SEQ)   // 8192

// ---------------- scratch (device globals: allocation-free) ----------------
__device__ __half g_Qh [BATCH * N_HEAD * SEQ * HD];    // Q single fp16
__device__ __half g_Kh [BATCH * N_HEAD * SEQ * HD];    // K single fp16
__device__ __half g_Vhi[BATCH * N_HEAD * SEQ * HD];    // V fp16 hi
__device__ __half g_Vlo[BATCH * N_HEAD * SEQ * HD];    // V fp16 lo

__device__ __half g_Xh[MTOT * C_EMBD];                 // x as fp16 (single)
__device__ __half g_Yh[MTOT * C_EMBD];                 // attn output as fp16
__device__ __half g_Wahi[3 * C_EMBD * C_EMBD];         // [N=3072][K=1024] fp16 (single-pass use)
__device__ __half g_Wphi[C_EMBD * C_EMBD];             // [N=1024][K=1024] fp16 hi
__device__ __half g_Wplo[C_EMBD * C_EMBD];             // fp16 lo residual

// ---------------- helpers ----------------
__device__ __forceinline__ uint32_t smem_u32(const void* p) {
    uint32_t a;
    asm("{ .reg .u64 t; cvta.to.shared.u64 t, %1; cvt.u32.u64 %0, t; }" : "=r"(a) : "l"(p));
    return a;
}

__device__ __forceinline__ void ldsm_x4(uint32_t& r0, uint32_t& r1,
                                        uint32_t& r2, uint32_t& r3, uint32_t addr) {
    asm volatile("ldmatrix.sync.aligned.m8n8.x4.shared.b16 {%0,%1,%2,%3}, [%4];"
                 : "=r"(r0), "=r"(r1), "=r"(r2), "=r"(r3) : "r"(addr));
}

__device__ __forceinline__ void ldsm_x4_t(uint32_t& r0, uint32_t& r1,
                                          uint32_t& r2, uint32_t& r3, uint32_t addr) {
    asm volatile("ldmatrix.sync.aligned.m8n8.x4.trans.shared.b16 {%0,%1,%2,%3}, [%4];"
                 : "=r"(r0), "=r"(r1), "=r"(r2), "=r"(r3) : "r"(addr));
}

__device__ __forceinline__ void mma_f16(float* c, const uint32_t* a, const uint32_t* b) {
    asm volatile(
        "mma.sync.aligned.m16n8k16.row.col.f32.f16.f16.f32 "
        "{%0,%1,%2,%3}, {%4,%5,%6,%7}, {%8,%9}, {%0,%1,%2,%3};"
        : "+f"(c[0]), "+f"(c[1]), "+f"(c[2]), "+f"(c[3])
        : "r"(a[0]), "r"(a[1]), "r"(a[2]), "r"(a[3]), "r"(b[0]), "r"(b[1]));
}

__device__ __forceinline__ void cp_async16(uint32_t dst, const void* src) {
    asm volatile("cp.async.cg.shared.global [%0], [%1], 16;" :: "r"(dst), "l"(src));
}
__device__ __forceinline__ void cp_commit() {
    asm volatile("cp.async.commit_group;");
}
template <int N>
__device__ __forceinline__ void cp_wait() {
    asm volatile("cp.async.wait_group %0;" :: "n"(N));
}

// ---------------- prep kernels ----------------
__global__ __launch_bounds__(256)
void tofp16_kernel(const float* __restrict__ X) {
    int i = blockIdx.x * 256 + threadIdx.x;           // float4 index
    float4 v = ((const float4*)X)[i];
    ((__half2*)g_Xh)[2*i+0] = __floats2half2_rn(v.x, v.y);
    ((__half2*)g_Xh)[2*i+1] = __floats2half2_rn(v.z, v.w);
}

// transpose (+ optional split):  W[K, N] fp32 -> Wt[N, K] fp16 (hi, and lo for proj)
__global__ __launch_bounds__(256)
void wsplit_kernel(const float* __restrict__ W, int which, int N) {
    __shared__ float t[32][33];
    __half* Hi = which ? g_Wphi : g_Wahi;
    const int K = C_EMBD;
    int n0 = blockIdx.x * 32, k0 = blockIdx.y * 32;
    int tx = threadIdx.x, ty = threadIdx.y;
#pragma unroll
    for (int s = 0; s < 4; s++) {
        int i = ty + 8 * s;
        t[i][tx] = W[(size_t)(k0 + i) * N + n0 + tx];
    }
    __syncthreads();
#pragma unroll
    for (int s = 0; s < 4; s++) {
        int i = ty + 8 * s;
        float v = t[tx][i];                            // W[k0+tx][n0+i]
        __half h = __float2half_rn(v);
        Hi[(size_t)(n0 + i) * K + k0 + tx] = h;
        if (which)
            g_Wplo[(size_t)(n0 + i) * K + k0 + tx] =
                __float2half_rn(v - __half2float(h));
    }
}

// ---------------- HMMA GEMM ----------------
// MODE 0 (QKV): W single fp16, 1 MMA pass; smem {A, Bh}.
// MODE 1 (proj): W hi+lo, 2 passes; smem {A, Bh, Bl}.
// 512 threads, CTA tile 128x128, warp tile 32x32, cp.async 3-stage, BK=32.
#define BKC     32
#define NCHUNK  (C_EMBD / BKC)          // 32
#define ROWB    80                       // smem row pitch bytes
#define MATB    (128 * ROWB)             // 10240 B
#define NSTAGE  3
#define A_OFF   0
#define BH_OFF  MATB
#define BL_OFF  (2 * MATB)

template <int MODE>
__global__ __launch_bounds__(512, 1)
void mma_gemm(const float* __restrict__ bias, float* __restrict__ Cout, int N)
{
    extern __shared__ char smem[];
    constexpr int NM = (MODE == 0) ? 2 : 3;          // matrices per stage
    constexpr int STAGEB = NM * MATB;

    const __half* Ain = (MODE == 0) ? g_Xh : g_Yh;
    const __half* Bhi = (MODE == 0) ? g_Wahi : g_Wphi;
    const __half* Blo = g_Wplo;                       // used only MODE 1

    const int K = C_EMBD;
    int tid = threadIdx.x;
    int lane = tid & 31, wid = tid >> 5;
    int wm = wid & 3, wn = wid >> 2;                  // warp tile 32(M) x 32(N)
    int bn = blockIdx.x * 128;
    int bm = blockIdx.y * 128;

    uint32_t sb = smem_u32(smem);

    int r_ld = tid >> 2;                  // 0..127
    int q_ld = tid & 3;                   // 16B slot
    const __half* pA  = Ain + (size_t)(bm + r_ld) * K + q_ld * 8;
    const __half* pBh = Bhi + (size_t)(bn + r_ld) * K + q_ld * 8;
    const __half* pBl = Blo + (size_t)(bn + r_ld) * K + q_ld * 8;
    uint32_t stoff = (uint32_t)(r_ld * ROWB + q_ld * 16);

    uint32_t a_row = (uint32_t)(wm * 32 + (lane & 15));          // + mf*16
    uint32_t a_colb = (uint32_t)(((lane >> 4) << 3) * 2);        // + ks*32
    int bq = lane >> 3;
    uint32_t b_row = (uint32_t)(wn * 32 + ((bq >> 1) << 3) + (lane & 7));  // + nb*16
    uint32_t b_colb = (uint32_t)(((bq & 1) << 3) * 2);                     // + ks*32

    float acc[2][4][4];
#pragma unroll
    for (int i = 0; i < 2; i++)
#pragma unroll
        for (int j = 0; j < 4; j++)
#pragma unroll
            for (int k = 0; k < 4; k++) acc[i][j][k] = 0.0f;

    // prologue: stages 0,1
#pragma unroll
    for (int st = 0; st < 2; st++) {
        uint32_t d = sb + st * STAGEB + stoff;
        int k0 = st * BKC;
        cp_async16(d + A_OFF,  pA  + k0);
        cp_async16(d + BH_OFF, pBh + k0);
        if (MODE == 1) cp_async16(d + BL_OFF, pBl + k0);
        cp_commit();
    }

    int stage_c = 0;
    int stage_l = 2;
    for (int ch = 0; ch < NCHUNK; ch++) {
        cp_wait<1>();
        __syncthreads();

        if (ch + 2 < NCHUNK) {
            uint32_t d = sb + stage_l * STAGEB + stoff;
            int k0 = (ch + 2) * BKC;
            cp_async16(d + A_OFF,  pA  + k0);
            cp_async16(d + BH_OFF, pBh + k0);
            if (MODE == 1) cp_async16(d + BL_OFF, pBl + k0);
        }
        cp_commit();

        uint32_t stage = sb + stage_c * STAGEB;
#pragma unroll
        for (int ks = 0; ks < 2; ks++) {
            uint32_t kb = (uint32_t)(ks * 32);
            uint32_t a[2][4];
#pragma unroll
            for (int mf = 0; mf < 2; mf++) {
                uint32_t ra = stage + (a_row + mf * 16) * ROWB + a_colb + kb;
                ldsm_x4(a[mf][0], a[mf][1], a[mf][2], a[mf][3], ra + A_OFF);
            }
            uint32_t bh[4][2];
#pragma unroll
            for (int nb = 0; nb < 2; nb++) {
                uint32_t rb = stage + (b_row + nb * 16) * ROWB + b_colb + kb;
                ldsm_x4(bh[2*nb][0], bh[2*nb][1], bh[2*nb+1][0], bh[2*nb+1][1], rb + BH_OFF);
            }
#pragma unroll
            for (int mf = 0; mf < 2; mf++)
#pragma unroll
                for (int nf = 0; nf < 4; nf++)
                    mma_f16(acc[mf][nf], a[mf], bh[nf]);
            if (MODE == 1) {
                uint32_t bl[4][2];
#pragma unroll
                for (int nb = 0; nb < 2; nb++) {
                    uint32_t rb = stage + (b_row + nb * 16) * ROWB + b_colb + kb;
                    ldsm_x4(bl[2*nb][0], bl[2*nb][1], bl[2*nb+1][0], bl[2*nb+1][1], rb + BL_OFF);
                }
#pragma unroll
                for (int mf = 0; mf < 2; mf++)
#pragma unroll
                    for (int nf = 0; nf < 4; nf++)
                        mma_f16(acc[mf][nf], a[mf], bl[nf]);
            }
        }

        stage_c = (stage_c == NSTAGE - 1) ? 0 : stage_c + 1;
        stage_l = (stage_l == NSTAGE - 1) ? 0 : stage_l + 1;
    }

    // epilogue: bias + write
#pragma unroll
    for (int mf = 0; mf < 2; mf++) {
#pragma unroll
        for (int nf = 0; nf < 4; nf++) {
            int m0 = bm + wm * 32 + mf * 16 + (lane >> 2);
            int n0 = bn + wn * 32 + nf * 8 + 2 * (lane & 3);
#pragma unroll
            for (int half = 0; half < 2; half++) {
                int m = m0 + half * 8;
                float v0 = acc[mf][nf][2 * half + 0] + bias[n0];
                float v1 = acc[mf][nf][2 * half + 1] + bias[n0 + 1];
                if (MODE == 0) {
                    int bb = m >> 11, t = m & 2047;
                    int which = n0 >> 10;
                    int cc = n0 & 1023;
                    int h = cc >> 6, d = cc & 63;
                    size_t idx = ((((size_t)bb * N_HEAD) + h) * SEQ + t) * HD + d;
                    if (which == 0) {
                        *(__half2*)&g_Qh[idx] = __floats2half2_rn(v0, v1);
                    } else if (which == 1) {
                        *(__half2*)&g_Kh[idx] = __floats2half2_rn(v0, v1);
                    } else {
                        __half h0 = __float2half_rn(v0);
                        __half h1 = __float2half_rn(v1);
                        *(__half2*)&g_Vhi[idx] = __halves2half2(h0, h1);
                        *(__half2*)&g_Vlo[idx] = __floats2half2_rn(
                            v0 - __half2float(h0), v1 - __half2float(h1));
                    }
                } else {
                    *(float2*)&Cout[(size_t)m * N + n0] = make_float2(v0, v1);
                }
            }
        }
    }
}

// ---------------------------------------------------------------------------
// HMMA flash attention: CTA = (b*h, 64-query block), 4 warps x 16 rows.
// 3-pass: S = Qh*Kh (1), PV = Ph*(Vhi+Vlo) (2). Softmax in registers.
// ---------------------------------------------------------------------------
#define FPITCH 144    // smem row pitch (bytes)
#define FTILE  (64 * FPITCH)   // 9216 B

__global__ __launch_bounds__(128)
void flash_mma_kernel()
{
    extern __shared__ char fsm[];
    char* pQ  = fsm;                    // 1 tile  (Q fp16)
    char* pK  = fsm + 1 * FTILE;        // 1 tile  (K fp16)
    char* pVH = fsm + 2 * FTILE;        // 2 tiles (V hi, V lo)
    const uint32_t Qs = smem_u32(pQ);
    const uint32_t Ks = smem_u32(pK);
    const uint32_t VH = smem_u32(pVH);

    int tid = threadIdx.x, lane = tid & 31, w = tid >> 5;
    int qb = (int)(gridDim.x - 1) - (int)blockIdx.x;    // heavy blocks first
    int bh = blockIdx.y;
    int q0 = qb * 64;
    size_t base = (size_t)bh * SEQ * HD;

    // load Q tile
    {
        int r = tid >> 3, s = tid & 7;
#pragma unroll
        for (int it = 0; it < 4; it++) {
            int rr = r + it * 16;
            size_t off = base + (size_t)(q0 + rr) * HD + s * 8;
            *(uint4*)(pQ + rr * FPITCH + s * 16) = *(const uint4*)(g_Qh + off);
        }
    }

    float m0 = -1e30f, m1 = -1e30f, l0 = 0.0f, l1 = 0.0f;
    float O[8][4];
#pragma unroll
    for (int i = 0; i < 8; i++)
#pragma unroll
        for (int j = 0; j < 4; j++) O[i][j] = 0.0f;

    for (int kb = 0; kb <= qb; kb++) {
        __syncthreads();
        int k0 = kb * 64;
        {
            int r = tid >> 3, s = tid & 7;
#pragma unroll
            for (int it = 0; it < 4; it++) {
                int rr = r + it * 16;
                size_t off = base + (size_t)(k0 + rr) * HD + s * 8;
                *(uint4*)(pK + rr * FPITCH + s * 16) = *(const uint4*)(g_Kh + off);
                *(uint4*)(pVH + rr * FPITCH + s * 16) = *(const uint4*)(g_Vhi + off);
                *(uint4*)(pVH + FTILE + rr * FPITCH + s * 16) = *(const uint4*)(g_Vlo + off);
            }
        }
        __syncthreads();

        // ---- S = Q K^T (single fp16 pass) ----
        float S[8][4];
#pragma unroll
        for (int i = 0; i < 8; i++)
#pragma unroll
            for (int j = 0; j < 4; j++) S[i][j] = 0.0f;

        int bq = lane >> 3;
#pragma unroll
        for (int s = 0; s < 4; s++) {
            uint32_t a[4];
            uint32_t ra = Qs + (w * 16 + (lane & 15)) * FPITCH + (lane >> 4) * 16 + s * 32;
            ldsm_x4(a[0], a[1], a[2], a[3], ra);
            uint32_t bh_[4][4];
#pragma unroll
            for (int nt = 0; nt < 4; nt++) {
                uint32_t rb = Ks + (nt * 16 + ((bq >> 1) << 3) + (lane & 7)) * FPITCH
                            + (bq & 1) * 16 + s * 32;
                ldsm_x4(bh_[nt][0], bh_[nt][1], bh_[nt][2], bh_[nt][3], rb);
            }
#pragma unroll
            for (int nt = 0; nt < 4; nt++) {
                mma_f16(S[2*nt],   a, &bh_[nt][0]);
                mma_f16(S[2*nt+1], a, &bh_[nt][2]);
            }
        }

        // ---- scale + causal mask ----
#pragma unroll
        for (int nb = 0; nb < 8; nb++)
#pragma unroll
            for (int e = 0; e < 4; e++) S[nb][e] *= 0.125f;

        if (kb == qb) {
            int rl0 = w * 16 + (lane >> 2);
#pragma unroll
            for (int nb = 0; nb < 8; nb++) {
                int c = nb * 8 + 2 * (lane & 3);
                if (c     > rl0)     S[nb][0] = -1e30f;
                if (c + 1 > rl0)     S[nb][1] = -1e30f;
                if (c     > rl0 + 8) S[nb][2] = -1e30f;
                if (c + 1 > rl0 + 8) S[nb][3] = -1e30f;
            }
        }

        // ---- online softmax ----
        float mx0 = -1e30f, mx1 = -1e30f;
#pragma unroll
        for (int nb = 0; nb < 8; nb++) {
            mx0 = fmaxf(mx0, fmaxf(S[nb][0], S[nb][1]));
            mx1 = fmaxf(mx1, fmaxf(S[nb][2], S[nb][3]));
        }
        mx0 = fmaxf(mx0, __shfl_xor_sync(0xffffffffu, mx0, 1));
        mx0 = fmaxf(mx0, __shfl_xor_sync(0xffffffffu, mx0, 2));
        mx1 = fmaxf(mx1, __shfl_xor_sync(0xffffffffu, mx1, 1));
        mx1 = fmaxf(mx1, __shfl_xor_sync(0xffffffffu, mx1, 2));
        float mn0 = fmaxf(m0, mx0), mn1 = fmaxf(m1, mx1);
        float corr0 = __expf(m0 - mn0), corr1 = __expf(m1 - mn1);
        float s0 = 0.0f, s1 = 0.0f;
#pragma unroll
        for (int nb = 0; nb < 8; nb++) {
            S[nb][0] = __expf(S[nb][0] - mn0); s0 += S[nb][0];
            S[nb][1] = __expf(S[nb][1] - mn0); s0 += S[nb][1];
            S[nb][2] = __expf(S[nb][2] - mn1); s1 += S[nb][2];
            S[nb][3] = __expf(S[nb][3] - mn1); s1 += S[nb][3];
        }
        s0 += __shfl_xor_sync(0xffffffffu, s0, 1);
        s0 += __shfl_xor_sync(0xffffffffu, s0, 2);
        s1 += __shfl_xor_sync(0xffffffffu, s1, 1);
        s1 += __shfl_xor_sync(0xffffffffu, s1, 2);
        l0 = l0 * corr0 + s0;
        l1 = l1 * corr1 + s1;
        m0 = mn0; m1 = mn1;
#pragma unroll
        for (int nb = 0; nb < 8; nb++) {
            O[nb][0] *= corr0; O[nb][1] *= corr0;
            O[nb][2] *= corr1; O[nb][3] *= corr1;
        }

        // ---- O += P V (fp16 2-pass, P packed single fp16) ----
#pragma unroll
        for (int s = 0; s < 4; s++) {
            uint32_t pa[4];
            __half2 p0 = __floats2half2_rn(S[2*s][0],   S[2*s][1]);
            __half2 p1 = __floats2half2_rn(S[2*s][2],   S[2*s][3]);
            __half2 p2 = __floats2half2_rn(S[2*s+1][0], S[2*s+1][1]);
            __half2 p3 = __floats2half2_rn(S[2*s+1][2], S[2*s+1][3]);
            pa[0] = *(uint32_t*)&p0;
            pa[1] = *(uint32_t*)&p1;
            pa[2] = *(uint32_t*)&p2;
            pa[3] = *(uint32_t*)&p3;
            uint32_t vh[4][4], vl[4][4];
#pragma unroll
            for (int nt = 0; nt < 4; nt++) {
                uint32_t rv = VH + (s * 16 + (lane & 7) + ((lane >> 3) & 1) * 8) * FPITCH
                            + nt * 32 + (lane >> 4) * 16;
                ldsm_x4_t(vh[nt][0], vh[nt][1], vh[nt][2], vh[nt][3], rv);
                ldsm_x4_t(vl[nt][0], vl[nt][1], vl[nt][2], vl[nt][3], rv + FTILE);
            }
#pragma unroll
            for (int nt = 0; nt < 4; nt++) {
                mma_f16(O[2*nt],   pa, &vh[nt][0]);
                mma_f16(O[2*nt+1], pa, &vh[nt][2]);
            }
#pragma unroll
            for (int nt = 0; nt < 4; nt++) {
                mma_f16(O[2*nt],   pa, &vl[nt][0]);
                mma_f16(O[2*nt+1], pa, &vl[nt][2]);
            }
        }
    }

    // ---- normalize + write Y (single fp16, [B,T,C]) ----
    int b = bh >> 4, h = bh & 15;
    int r0g = q0 + w * 16 + (lane >> 2);
    int dcol = 2 * (lane & 3);
    float inv0 = 1.0f / l0, inv1 = 1.0f / l1;
#pragma unroll
    for (int nb = 0; nb < 8; nb++) {
        int d = nb * 8 + dcol;
        {
            size_t idx = ((size_t)(b * SEQ + r0g)) * C_EMBD + h * HD + d;
            *(__half2*)&g_Yh[idx] = __floats2half2_rn(O[nb][0] * inv0, O[nb][1] * inv0);
        }
        {
            size_t idx = ((size_t)(b * SEQ + r0g + 8)) * C_EMBD + h * HD + d;
            *(__half2*)&g_Yh[idx] = __floats2half2_rn(O[nb][2] * inv1, O[nb][3] * inv1);
        }
    }
}

// ---------------------------------------------------------------------------
extern "C" void kernel_launch(void* const* d_in, const int* in_sizes, int n_in,
                              void* d_out, int out_size)
{
    const float* x      = (const float*)d_in[0];
    const float* W_attn = (const float*)d_in[1];
    const float* b_attn = (const float*)d_in[2];
    const float* W_proj = (const float*)d_in[3];
    const float* b_proj = (const float*)d_in[4];
    float* out = (float*)d_out;

    (void)in_sizes; (void)n_in; (void)out_size;

    static const int FLASH_SMEM = 4 * FTILE;                        // 36864 B
    static const int GEMM0_SMEM = NSTAGE * 2 * MATB;                // 61440 B
    static const int GEMM1_SMEM = NSTAGE * 3 * MATB;                // 92160 B
    cudaFuncSetAttribute(flash_mma_kernel,
                         cudaFuncAttributeMaxDynamicSharedMemorySize, FLASH_SMEM);
    cudaFuncSetAttribute(mma_gemm<0>,
                         cudaFuncAttributeMaxDynamicSharedMemorySize, GEMM0_SMEM);
    cudaFuncSetAttribute(mma_gemm<1>,
                         cudaFuncAttributeMaxDynamicSharedMemorySize, GEMM1_SMEM);

    // 0) prep: x -> fp16; transpose weights (split for proj only)
    tofp16_kernel<<<MTOT * C_EMBD / 4 / 256, 256>>>(x);
    wsplit_kernel<<<dim3(3 * C_EMBD / 32, C_EMBD / 32), dim3(32, 8)>>>(W_attn, 0, 3 * C_EMBD);
    wsplit_kernel<<<dim3(C_EMBD / 32, C_EMBD / 32), dim3(32, 8)>>>(W_proj, 1, C_EMBD);

    // 1) QKV GEMM (fp16 single-pass) + bias -> Q,K single fp16; V hi+lo
    mma_gemm<0><<<dim3(3 * C_EMBD / 128, MTOT / 128), 512, GEMM0_SMEM>>>(
        b_attn, nullptr, 3 * C_EMBD);

    // 2) causal flash attention (fp16 3-pass) -> Y fp16
    flash_mma_kernel<<<dim3(SEQ / 64, BATCH * N_HEAD), 128, FLASH_SMEM>>>();

    // 3) output projection (fp16 2-pass) + bias -> d_out
    mma_gemm<1><<<dim3(C_EMBD / 128, MTOT / 128), 512, GEMM1_SMEM>>>(
        b_proj, out, C_EMBD);
}

// round 13
// speedup vs baseline: 2.2142x; 1.2327x over previous
#include <cuda_runtime.h>
#include <cuda_fp16.h>
#include <cstdint>

#define N_HEAD 16
#define C_EMBD 1024
#define HD     64
#define BATCH  4
#define SEQ    2048
#define MTOT   (BATCH * SEQ)   // 8192

// ---------------- scratch (device globals: allocation-free) ----------------
__device__ __half g_Qh[BATCH * N_HEAD * SEQ * HD];     // Q fp16
__device__ __half g_Kh[BATCH * N_HEAD * SEQ * HD];     // K fp16
__device__ __half g_Vh[BATCH * N_HEAD * SEQ * HD];     // V fp16

__device__ __half g_Xh[MTOT * C_EMBD];                 // x as fp16
__device__ __half g_Yh[MTOT * C_EMBD];                 // attn output as fp16
__device__ __half g_Wa[3 * C_EMBD * C_EMBD];           // [N=3072][K=1024] fp16
__device__ __half g_Wp[C_EMBD * C_EMBD];               // [N=1024][K=1024] fp16

// ---------------- helpers ----------------
__device__ __forceinline__ uint32_t smem_u32(const void* p) {
    uint32_t a;
    asm("{ .reg .u64 t; cvta.to.shared.u64 t, %1; cvt.u32.u64 %0, t; }" : "=r"(a) : "l"(p));
    return a;
}

__device__ __forceinline__ void ldsm_x4(uint32_t& r0, uint32_t& r1,
                                        uint32_t& r2, uint32_t& r3, uint32_t addr) {
    asm volatile("ldmatrix.sync.aligned.m8n8.x4.shared.b16 {%0,%1,%2,%3}, [%4];"
                 : "=r"(r0), "=r"(r1), "=r"(r2), "=r"(r3) : "r"(addr));
}

__device__ __forceinline__ void ldsm_x4_t(uint32_t& r0, uint32_t& r1,
                                          uint32_t& r2, uint32_t& r3, uint32_t addr) {
    asm volatile("ldmatrix.sync.aligned.m8n8.x4.trans.shared.b16 {%0,%1,%2,%3}, [%4];"
                 : "=r"(r0), "=r"(r1), "=r"(r2), "=r"(r3) : "r"(addr));
}

__device__ __forceinline__ void mma_f16(float* c, const uint32_t* a, const uint32_t* b) {
    asm volatile(
        "mma.sync.aligned.m16n8k16.row.col.f32.f16.f16.f32 "
        "{%0,%1,%2,%3}, {%4,%5,%6,%7}, {%8,%9}, {%0,%1,%2,%3};"
        : "+f"(c[0]), "+f"(c[1]), "+f"(c[2]), "+f"(c[3])
        : "r"(a[0]), "r"(a[1]), "r"(a[2]), "r"(a[3]), "r"(b[0]), "r"(b[1]));
}

__device__ __forceinline__ void cp_async16(uint32_t dst, const void* src) {
    asm volatile("cp.async.cg.shared.global [%0], [%1], 16;" :: "r"(dst), "l"(src));
}
__device__ __forceinline__ void cp_commit() {
    asm volatile("cp.async.commit_group;");
}
template <int N>
__device__ __forceinline__ void cp_wait() {
    asm volatile("cp.async.wait_group %0;" :: "n"(N));
}

// ---------------- prep kernels ----------------
__global__ __launch_bounds__(256)
void tofp16_kernel(const float* __restrict__ X) {
    int i = blockIdx.x * 256 + threadIdx.x;           // float4 index
    float4 v = ((const float4*)X)[i];
    ((__half2*)g_Xh)[2*i+0] = __floats2half2_rn(v.x, v.y);
    ((__half2*)g_Xh)[2*i+1] = __floats2half2_rn(v.z, v.w);
}

// transpose:  W[K, N] fp32 -> Wt[N, K] fp16
__global__ __launch_bounds__(256)
void wt_kernel(const float* __restrict__ W, int which, int N) {
    __shared__ float t[32][33];
    __half* Dst = which ? g_Wp : g_Wa;
    const int K = C_EMBD;
    int n0 = blockIdx.x * 32, k0 = blockIdx.y * 32;
    int tx = threadIdx.x, ty = threadIdx.y;
#pragma unroll
    for (int s = 0; s < 4; s++) {
        int i = ty + 8 * s;
        t[i][tx] = W[(size_t)(k0 + i) * N + n0 + tx];
    }
    __syncthreads();
#pragma unroll
    for (int s = 0; s < 4; s++) {
        int i = ty + 8 * s;
        Dst[(size_t)(n0 + i) * K + k0 + tx] = __float2half_rn(t[tx][i]);
    }
}

// ---------------- HMMA GEMM (fp16 single pass) ----------------
// 512 threads, CTA tile 128x128, warp tile 32x32, cp.async 3-stage, BK=64.
#define BKC     64
#define NCHUNK  (C_EMBD / BKC)          // 16
#define ROWB    144                      // smem row pitch bytes (128B data + 16 pad)
#define MATB    (128 * ROWB)             // 18432 B
#define STAGEB  (2 * MATB)               // 36864 B (A, B)
#define NSTAGE  3
#define A_OFF   0
#define B_OFF   MATB

template <int MODE>   // 0: QKV gemm (scatter Q/K/V fp16), 1: proj gemm (fp32 out)
__global__ __launch_bounds__(512, 1)
void mma_gemm(const float* __restrict__ bias, float* __restrict__ Cout, int N)
{
    extern __shared__ char smem[];

    const __half* Ain = (MODE == 0) ? g_Xh : g_Yh;
    const __half* Bw  = (MODE == 0) ? g_Wa : g_Wp;

    const int K = C_EMBD;
    int tid = threadIdx.x;
    int lane = tid & 31, wid = tid >> 5;
    int wm = wid & 3, wn = wid >> 2;                  // warp tile 32(M) x 32(N)
    int bn = blockIdx.x * 128;
    int bm = blockIdx.y * 128;

    uint32_t sb = smem_u32(smem);

    int r_ld = tid >> 2;                  // 0..127
    int q_ld = tid & 3;                   // 16B slot (of first 64B half)
    const __half* pA = Ain + (size_t)(bm + r_ld) * K + q_ld * 8;
    const __half* pB = Bw  + (size_t)(bn + r_ld) * K + q_ld * 8;
    uint32_t stoff = (uint32_t)(r_ld * ROWB + q_ld * 16);

    uint32_t a_row = (uint32_t)(wm * 32 + (lane & 15));          // + mf*16
    uint32_t a_colb = (uint32_t)((lane >> 4) * 16);              // + ks*32
    int bq = lane >> 3;
    uint32_t b_row = (uint32_t)(wn * 32 + ((bq >> 1) << 3) + (lane & 7));  // + nb*16
    uint32_t b_colb = (uint32_t)((bq & 1) * 16);                           // + ks*32

    float acc[2][4][4];
#pragma unroll
    for (int i = 0; i < 2; i++)
#pragma unroll
        for (int j = 0; j < 4; j++)
#pragma unroll
            for (int k = 0; k < 4; k++) acc[i][j][k] = 0.0f;

    // prologue: stages 0,1
#pragma unroll
    for (int st = 0; st < 2; st++) {
        uint32_t d = sb + st * STAGEB + stoff;
        int k0 = st * BKC;
        cp_async16(d + A_OFF,      pA + k0);
        cp_async16(d + A_OFF + 64, pA + k0 + 32);
        cp_async16(d + B_OFF,      pB + k0);
        cp_async16(d + B_OFF + 64, pB + k0 + 32);
        cp_commit();
    }

    int stage_c = 0;
    int stage_l = 2;
    for (int ch = 0; ch < NCHUNK; ch++) {
        cp_wait<1>();
        __syncthreads();

        if (ch + 2 < NCHUNK) {
            uint32_t d = sb + stage_l * STAGEB + stoff;
            int k0 = (ch + 2) * BKC;
            cp_async16(d + A_OFF,      pA + k0);
            cp_async16(d + A_OFF + 64, pA + k0 + 32);
            cp_async16(d + B_OFF,      pB + k0);
            cp_async16(d + B_OFF + 64, pB + k0 + 32);
        }
        cp_commit();

        uint32_t stage = sb + stage_c * STAGEB;
#pragma unroll
        for (int ks = 0; ks < 4; ks++) {
            uint32_t kb = (uint32_t)(ks * 32);
            uint32_t a[2][4];
#pragma unroll
            for (int mf = 0; mf < 2; mf++) {
                uint32_t ra = stage + (a_row + mf * 16) * ROWB + a_colb + kb;
                ldsm_x4(a[mf][0], a[mf][1], a[mf][2], a[mf][3], ra + A_OFF);
            }
            uint32_t bh[4][2];
#pragma unroll
            for (int nb = 0; nb < 2; nb++) {
                uint32_t rb = stage + (b_row + nb * 16) * ROWB + b_colb + kb;
                ldsm_x4(bh[2*nb][0], bh[2*nb][1], bh[2*nb+1][0], bh[2*nb+1][1], rb + B_OFF);
            }
#pragma unroll
            for (int mf = 0; mf < 2; mf++)
#pragma unroll
                for (int nf = 0; nf < 4; nf++)
                    mma_f16(acc[mf][nf], a[mf], bh[nf]);
        }

        stage_c = (stage_c == NSTAGE - 1) ? 0 : stage_c + 1;
        stage_l = (stage_l == NSTAGE - 1) ? 0 : stage_l + 1;
    }

    // epilogue: bias + write
#pragma unroll
    for (int mf = 0; mf < 2; mf++) {
#pragma unroll
        for (int nf = 0; nf < 4; nf++) {
            int m0 = bm + wm * 32 + mf * 16 + (lane >> 2);
            int n0 = bn + wn * 32 + nf * 8 + 2 * (lane & 3);
#pragma unroll
            for (int half = 0; half < 2; half++) {
                int m = m0 + half * 8;
                float v0 = acc[mf][nf][2 * half + 0] + bias[n0];
                float v1 = acc[mf][nf][2 * half + 1] + bias[n0 + 1];
                if (MODE == 0) {
                    int bb = m >> 11, t = m & 2047;
                    int which = n0 >> 10;
                    int cc = n0 & 1023;
                    int h = cc >> 6, d = cc & 63;
                    __half* Dst = (which == 0) ? g_Qh : (which == 1) ? g_Kh : g_Vh;
                    size_t idx = ((((size_t)bb * N_HEAD) + h) * SEQ + t) * HD + d;
                    *(__half2*)&Dst[idx] = __floats2half2_rn(v0, v1);
                } else {
                    *(float2*)&Cout[(size_t)m * N + n0] = make_float2(v0, v1);
                }
            }
        }
    }
}

// ---------------------------------------------------------------------------
// HMMA flash attention: CTA = (b*h, 64-query block), 4 warps x 16 rows.
// 2-pass: S = Q*K (1 MMA pass), PV = P*V (1 MMA pass). Softmax in registers.
// ---------------------------------------------------------------------------
#define FPITCH 144    // smem row pitch (bytes)
#define FTILE  (64 * FPITCH)   // 9216 B

__global__ __launch_bounds__(128)
void flash_mma_kernel()
{
    extern __shared__ char fsm[];
    char* pQ = fsm;                     // 1 tile  (Q fp16)
    char* pK = fsm + 1 * FTILE;         // 1 tile  (K fp16)
    char* pV = fsm + 2 * FTILE;         // 1 tile  (V fp16)
    const uint32_t Qs = smem_u32(pQ);
    const uint32_t Ks = smem_u32(pK);
    const uint32_t Vs = smem_u32(pV);

    int tid = threadIdx.x, lane = tid & 31, w = tid >> 5;
    int qb = (int)(gridDim.x - 1) - (int)blockIdx.x;    // heavy blocks first
    int bh = blockIdx.y;
    int q0 = qb * 64;
    size_t base = (size_t)bh * SEQ * HD;

    // load Q tile
    {
        int r = tid >> 3, s = tid & 7;
#pragma unroll
        for (int it = 0; it < 4; it++) {
            int rr = r + it * 16;
            size_t off = base + (size_t)(q0 + rr) * HD + s * 8;
            *(uint4*)(pQ + rr * FPITCH + s * 16) = *(const uint4*)(g_Qh + off);
        }
    }

    float m0 = -1e30f, m1 = -1e30f, l0 = 0.0f, l1 = 0.0f;
    float O[8][4];
#pragma unroll
    for (int i = 0; i < 8; i++)
#pragma unroll
        for (int j = 0; j < 4; j++) O[i][j] = 0.0f;

    for (int kb = 0; kb <= qb; kb++) {
        __syncthreads();
        int k0 = kb * 64;
        {
            int r = tid >> 3, s = tid & 7;
#pragma unroll
            for (int it = 0; it < 4; it++) {
                int rr = r + it * 16;
                size_t off = base + (size_t)(k0 + rr) * HD + s * 8;
                *(uint4*)(pK + rr * FPITCH + s * 16) = *(const uint4*)(g_Kh + off);
                *(uint4*)(pV + rr * FPITCH + s * 16) = *(const uint4*)(g_Vh + off);
            }
        }
        __syncthreads();

        // ---- S = Q K^T (single fp16 pass) ----
        float S[8][4];
#pragma unroll
        for (int i = 0; i < 8; i++)
#pragma unroll
            for (int j = 0; j < 4; j++) S[i][j] = 0.0f;

        int bq = lane >> 3;
#pragma unroll
        for (int s = 0; s < 4; s++) {
            uint32_t a[4];
            uint32_t ra = Qs + (w * 16 + (lane & 15)) * FPITCH + (lane >> 4) * 16 + s * 32;
            ldsm_x4(a[0], a[1], a[2], a[3], ra);
            uint32_t bh_[4][4];
#pragma unroll
            for (int nt = 0; nt < 4; nt++) {
                uint32_t rb = Ks + (nt * 16 + ((bq >> 1) << 3) + (lane & 7)) * FPITCH
                            + (bq & 1) * 16 + s * 32;
                ldsm_x4(bh_[nt][0], bh_[nt][1], bh_[nt][2], bh_[nt][3], rb);
            }
#pragma unroll
            for (int nt = 0; nt < 4; nt++) {
                mma_f16(S[2*nt],   a, &bh_[nt][0]);
                mma_f16(S[2*nt+1], a, &bh_[nt][2]);
            }
        }

        // ---- scale + causal mask ----
#pragma unroll
        for (int nb = 0; nb < 8; nb++)
#pragma unroll
            for (int e = 0; e < 4; e++) S[nb][e] *= 0.125f;

        if (kb == qb) {
            int rl0 = w * 16 + (lane >> 2);
#pragma unroll
            for (int nb = 0; nb < 8; nb++) {
                int c = nb * 8 + 2 * (lane & 3);
                if (c     > rl0)     S[nb][0] = -1e30f;
                if (c + 1 > rl0)     S[nb][1] = -1e30f;
                if (c     > rl0 + 8) S[nb][2] = -1e30f;
                if (c + 1 > rl0 + 8) S[nb][3] = -1e30f;
            }
        }

        // ---- online softmax ----
        float mx0 = -1e30f, mx1 = -1e30f;
#pragma unroll
        for (int nb = 0; nb < 8; nb++) {
            mx0 = fmaxf(mx0, fmaxf(S[nb][0], S[nb][1]));
            mx1 = fmaxf(mx1, fmaxf(S[nb][2], S[nb][3]));
        }
        mx0 = fmaxf(mx0, __shfl_xor_sync(0xffffffffu, mx0, 1));
        mx0 = fmaxf(mx0, __shfl_xor_sync(0xffffffffu, mx0, 2));
        mx1 = fmaxf(mx1, __shfl_xor_sync(0xffffffffu, mx1, 1));
        mx1 = fmaxf(mx1, __shfl_xor_sync(0xffffffffu, mx1, 2));
        float mn0 = fmaxf(m0, mx0), mn1 = fmaxf(m1, mx1);
        float corr0 = __expf(m0 - mn0), corr1 = __expf(m1 - mn1);
        float s0 = 0.0f, s1 = 0.0f;
#pragma unroll
        for (int nb = 0; nb < 8; nb++) {
            S[nb][0] = __expf(S[nb][0] - mn0); s0 += S[nb][0];
            S[nb][1] = __expf(S[nb][1] - mn0); s0 += S[nb][1];
            S[nb][2] = __expf(S[nb][2] - mn1); s1 += S[nb][2];
            S[nb][3] = __expf(S[nb][3] - mn1); s1 += S[nb][3];
        }
        s0 += __shfl_xor_sync(0xffffffffu, s0, 1);
        s0 += __shfl_xor_sync(0xffffffffu, s0, 2);
        s1 += __shfl_xor_sync(0xffffffffu, s1, 1);
        s1 += __shfl_xor_sync(0xffffffffu, s1, 2);
        l0 = l0 * corr0 + s0;
        l1 = l1 * corr1 + s1;
        m0 = mn0; m1 = mn1;
#pragma unroll
        for (int nb = 0; nb < 8; nb++) {
            O[nb][0] *= corr0; O[nb][1] *= corr0;
            O[nb][2] *= corr1; O[nb][3] *= corr1;
        }

        // ---- O += P V (single fp16 pass) ----
#pragma unroll
        for (int s = 0; s < 4; s++) {
            uint32_t pa[4];
            __half2 p0 = __floats2half2_rn(S[2*s][0],   S[2*s][1]);
            __half2 p1 = __floats2half2_rn(S[2*s][2],   S[2*s][3]);
            __half2 p2 = __floats2half2_rn(S[2*s+1][0], S[2*s+1][1]);
            __half2 p3 = __floats2half2_rn(S[2*s+1][2], S[2*s+1][3]);
            pa[0] = *(uint32_t*)&p0;
            pa[1] = *(uint32_t*)&p1;
            pa[2] = *(uint32_t*)&p2;
            pa[3] = *(uint32_t*)&p3;
            uint32_t vh[4][4];
#pragma unroll
            for (int nt = 0; nt < 4; nt++) {
                uint32_t rv = Vs + (s * 16 + (lane & 7) + ((lane >> 3) & 1) * 8) * FPITCH
                            + nt * 32 + (lane >> 4) * 16;
                ldsm_x4_t(vh[nt][0], vh[nt][1], vh[nt][2], vh[nt][3], rv);
            }
#pragma unroll
            for (int nt = 0; nt < 4; nt++) {
                mma_f16(O[2*nt],   pa, &vh[nt][0]);
                mma_f16(O[2*nt+1], pa, &vh[nt][2]);
            }
        }
    }

    // ---- normalize + write Y (fp16, [B,T,C]) ----
    int b = bh >> 4, h = bh & 15;
    int r0g = q0 + w * 16 + (lane >> 2);
    int dcol = 2 * (lane & 3);
    float inv0 = 1.0f / l0, inv1 = 1.0f / l1;
#pragma unroll
    for (int nb = 0; nb < 8; nb++) {
        int d = nb * 8 + dcol;
        {
            size_t idx = ((size_t)(b * SEQ + r0g)) * C_EMBD + h * HD + d;
            *(__half2*)&g_Yh[idx] = __floats2half2_rn(O[nb][0] * inv0, O[nb][1] * inv0);
        }
        {
            size_t idx = ((size_t)(b * SEQ + r0g + 8)) * C_EMBD + h * HD + d;
            *(__half2*)&g_Yh[idx] = __floats2half2_rn(O[nb][2] * inv1, O[nb][3] * inv1);
        }
    }
}

// ---------------------------------------------------------------------------
extern "C" void kernel_launch(void* const* d_in, const int* in_sizes, int n_in,
                              void* d_out, int out_size)
{
    const float* x      = (const float*)d_in[0];
    const float* W_attn = (const float*)d_in[1];
    const float* b_attn = (const float*)d_in[2];
    const float* W_proj = (const float*)d_in[3];
    const float* b_proj = (const float*)d_in[4];
    float* out = (float*)d_out;

    (void)in_sizes; (void)n_in; (void)out_size;

    static const int FLASH_SMEM = 3 * FTILE;                        // 27648 B
    static const int GEMM_SMEM  = NSTAGE * STAGEB;                  // 110592 B
    cudaFuncSetAttribute(flash_mma_kernel,
                         cudaFuncAttributeMaxDynamicSharedMemorySize, FLASH_SMEM);
    cudaFuncSetAttribute(mma_gemm<0>,
                         cudaFuncAttributeMaxDynamicSharedMemorySize, GEMM_SMEM);
    cudaFuncSetAttribute(mma_gemm<1>,
                         cudaFuncAttributeMaxDynamicSharedMemorySize, GEMM_SMEM);

    // 0) prep: x -> fp16; transpose weights -> fp16
    tofp16_kernel<<<MTOT * C_EMBD / 4 / 256, 256>>>(x);
    wt_kernel<<<dim3(3 * C_EMBD / 32, C_EMBD / 32), dim3(32, 8)>>>(W_attn, 0, 3 * C_EMBD);
    wt_kernel<<<dim3(C_EMBD / 32, C_EMBD / 32), dim3(32, 8)>>>(W_proj, 1, C_EMBD);

    // 1) QKV GEMM (fp16 single-pass) + bias -> Q/K/V fp16 [B,H,T,hd]
    mma_gemm<0><<<dim3(3 * C_EMBD / 128, MTOT / 128), 512, GEMM_SMEM>>>(
        b_attn, nullptr, 3 * C_EMBD);

    // 2) causal flash attention (fp16 2-pass) -> Y fp16
    flash_mma_kernel<<<dim3(SEQ / 64, BATCH * N_HEAD), 128, FLASH_SMEM>>>();

    // 3) output projection (fp16 single-pass) + bias -> d_out
    mma_gemm<1><<<dim3(C_EMBD / 128, MTOT / 128), 512, GEMM_SMEM>>>(
        b_proj, out, C_EMBD);
}